// round 5
// baseline (speedup 1.0000x reference)
#include <cuda_runtime.h>
#include <cuda_bf16.h>
#include <math.h>
#include <stdint.h>

#define L_SEQ 1024
#define DM 768
#define DI 1536
#define DSTATE 16
#define DCONV 4
#define DTRANK 48
#define NLAYER 4
#define VOCAB 50280
#define DBL_W (DTRANK + 2*DSTATE)  // 80

typedef unsigned long long ull;

// ---------------- scratch (device globals) ---------------------------------
__device__ float g_h [L_SEQ*DM];
__device__ float g_hn[L_SEQ*DM];
__device__ float g_xz[L_SEQ*2*DI];
__device__ float g_xc[L_SEQ*DI];
__device__ float g_dbl[L_SEQ*DBL_W];
__device__ float g_dt[L_SEQ*DI];
__device__ float g_y [L_SEQ*DI];

// ---------------- f32x2 helpers --------------------------------------------
__device__ __forceinline__ ull f32x2_dup(float v){
    ull r; asm("mov.b64 %0, {%1, %1};" : "=l"(r) : "f"(v)); return r;
}
__device__ __forceinline__ ull f32x2_fma(ull a, ull b, ull c){
    ull d; asm("fma.rn.f32x2 %0, %1, %2, %3;" : "=l"(d) : "l"(a), "l"(b), "l"(c));
    return d;
}
__device__ __forceinline__ void f32x2_unpack(float& lo, float& hi, ull v){
    asm("mov.b64 {%0, %1}, %2;" : "=f"(lo), "=f"(hi) : "l"(v));
}

// ---------------- embedding gather ----------------------------------------
__global__ void embed_kernel(const int* __restrict__ ids,
                             const float* __restrict__ emb)
{
    int l = blockIdx.x;
    int id = ids[l];
    const float4* src = (const float4*)(emb + (size_t)id * DM);
    float4* dst = (float4*)(g_h + (size_t)l * DM);
    dst[threadIdx.x] = src[threadIdx.x];
}

// ---------------- rmsnorm --------------------------------------------------
__global__ void rmsnorm_kernel(const float* __restrict__ in,
                               float* __restrict__ out,
                               const float* __restrict__ w)
{
    int l = blockIdx.x;
    const float* x = in + (size_t)l * DM;
    float ss = 0.f;
    for (int i = threadIdx.x; i < DM; i += 256) {
        float v = x[i];
        ss = fmaf(v, v, ss);
    }
    #pragma unroll
    for (int off = 16; off >= 1; off >>= 1)
        ss += __shfl_xor_sync(0xffffffffu, ss, off);

    __shared__ float red[8];
    __shared__ float scale_s;
    int warp = threadIdx.x >> 5, lane = threadIdx.x & 31;
    if (lane == 0) red[warp] = ss;
    __syncthreads();
    if (threadIdx.x == 0) {
        float t = 0.f;
        #pragma unroll
        for (int i = 0; i < 8; i++) t += red[i];
        scale_s = rsqrtf(t / (float)DM + 1e-5f);
    }
    __syncthreads();
    float scale = scale_s;
    for (int i = threadIdx.x; i < DM; i += 256)
        out[(size_t)l * DM + i] = x[i] * scale * w[i];
}

// ---------------- depthwise causal conv (k=4) + bias + silu ----------------
__global__ void conv_silu_kernel(const float* __restrict__ cw,
                                 const float* __restrict__ cb)
{
    int idx = blockIdx.x * blockDim.x + threadIdx.x;
    int l = idx / DI;
    int d = idx - l * DI;
    float4 wv = *(const float4*)(cw + (size_t)d * 4);
    float acc = cb[d];
    const float* wj = (const float*)&wv;
    #pragma unroll
    for (int j = 0; j < DCONV; j++) {
        int ll = l - (DCONV - 1) + j;
        if (ll >= 0) acc = fmaf(wj[j], g_xz[(size_t)ll * 2 * DI + d], acc);
    }
    acc = acc / (1.f + __expf(-acc));
    g_xc[idx] = acc;
}

// ---------------- selective scan -------------------------------------------
__global__ void scan_kernel(const float* __restrict__ A_log)
{
    int gw   = (blockIdx.x * blockDim.x + threadIdx.x) >> 5;
    int lane = threadIdx.x & 31;
    int n    = lane & 15;
    int ch   = gw * 2 + (lane >> 4);

    float Aval = -__expf(A_log[(size_t)ch * DSTATE + n]);
    float s = 0.f;
    for (int l = 0; l < L_SEQ; l++) {
        float dtv = g_dt [(size_t)l * DI + ch];
        float xcv = g_xc [(size_t)l * DI + ch];
        float Bv  = g_dbl[(size_t)l * DBL_W + DTRANK + n];
        float Cv  = g_dbl[(size_t)l * DBL_W + DTRANK + DSTATE + n];
        s = __expf(dtv * Aval) * s + dtv * Bv * xcv;
        float p = s * Cv;
        p += __shfl_xor_sync(0xffffffffu, p, 1);
        p += __shfl_xor_sync(0xffffffffu, p, 2);
        p += __shfl_xor_sync(0xffffffffu, p, 4);
        p += __shfl_xor_sync(0xffffffffu, p, 8);
        if (n == 0) g_y[(size_t)l * DI + ch] = p;
    }
}

// ---------------- y = (y + xc*D) * silu(z) ---------------------------------
__global__ void y_epi_kernel(const float* __restrict__ Dp)
{
    int idx = blockIdx.x * blockDim.x + threadIdx.x;
    int l = idx / DI;
    int d = idx - l * DI;
    float z  = g_xz[(size_t)l * 2 * DI + DI + d];
    float yv = g_y[idx] + g_xc[idx] * Dp[d];
    yv *= z / (1.f + __expf(-z));
    g_y[idx] = yv;
}

// ---------------- fp32 TN GEMM (small shapes: x_proj, dt_proj) -------------
#define GBM 128
#define GBN 64
#define GBK 16

template<int EPI>
__global__ __launch_bounds__(256)
void gemm_tn(const float* __restrict__ A, int lda,
             const float* __restrict__ B, int ldb,
             float* __restrict__ C, int ldc,
             int N, int K, const float* __restrict__ bias)
{
    __shared__ float As[GBK][GBM + 4];
    __shared__ float Bs[GBK][GBN + 4];

    const int bm  = blockIdx.y * GBM;
    const int bn  = blockIdx.x * GBN;
    const int tid = threadIdx.x;
    const int tx  = tid & 15;
    const int ty  = tid >> 4;
    const int a_row = tid >> 1;
    const int a_k   = (tid & 1) * 8;
    const int b_row = tid >> 2;
    const int b_k   = (tid & 3) * 4;

    float acc[8][4];
    #pragma unroll
    for (int i = 0; i < 8; i++)
        #pragma unroll
        for (int j = 0; j < 4; j++) acc[i][j] = 0.f;

    const float* Aptr = A + (size_t)(bm + a_row) * lda + a_k;
    const int gbn = bn + b_row;
    const float* Bptr = (gbn < N) ? (B + (size_t)gbn * ldb + b_k) : 0;

    for (int k0 = 0; k0 < K; k0 += GBK) {
        float4 av0 = *(const float4*)(Aptr + k0);
        float4 av1 = *(const float4*)(Aptr + k0 + 4);
        float4 bv  = Bptr ? *(const float4*)(Bptr + k0)
                          : make_float4(0.f, 0.f, 0.f, 0.f);

        As[a_k + 0][a_row] = av0.x; As[a_k + 1][a_row] = av0.y;
        As[a_k + 2][a_row] = av0.z; As[a_k + 3][a_row] = av0.w;
        As[a_k + 4][a_row] = av1.x; As[a_k + 5][a_row] = av1.y;
        As[a_k + 6][a_row] = av1.z; As[a_k + 7][a_row] = av1.w;
        Bs[b_k + 0][b_row] = bv.x;  Bs[b_k + 1][b_row] = bv.y;
        Bs[b_k + 2][b_row] = bv.z;  Bs[b_k + 3][b_row] = bv.w;
        __syncthreads();

        #pragma unroll
        for (int kk = 0; kk < GBK; kk++) {
            float ar[8], br[4];
            #pragma unroll
            for (int i = 0; i < 8; i++) ar[i] = As[kk][ty * 8 + i];
            #pragma unroll
            for (int j = 0; j < 4; j++) br[j] = Bs[kk][tx * 4 + j];
            #pragma unroll
            for (int i = 0; i < 8; i++)
                #pragma unroll
                for (int j = 0; j < 4; j++)
                    acc[i][j] = fmaf(ar[i], br[j], acc[i][j]);
        }
        __syncthreads();
    }

    #pragma unroll
    for (int i = 0; i < 8; i++) {
        int m = bm + ty * 8 + i;
        #pragma unroll
        for (int j = 0; j < 4; j++) {
            int n = bn + tx * 4 + j;
            if (n < N) {
                float v = acc[i][j];
                if (EPI == 1) {
                    v += bias[n];
                    v = fmaxf(v, 0.f) + log1pf(__expf(-fabsf(v)));
                }
                if (EPI == 2) C[(size_t)m * ldc + n] += v;
                else          C[(size_t)m * ldc + n] = v;
            }
        }
    }
}

// ---------------- f32x2 packed-FMA TN GEMM (big shapes) --------------------
// C[m][n] = sum_k A[m][k]*B[n][k].  BM=128 BN=64 BK=16, 256 threads.
// Microtile: 4 m-pairs x 4 n per thread, acc in packed f32x2.
// B duplicated into (b,b) pairs in smem; A m-pairs read as 64-bit words.
// Register prefetch of next K chunk overlaps math phase.
#define XBM 128
#define XBN 64
#define XBK 16

template<int EPI>
__global__ __launch_bounds__(256)
void gemm_x2(const float* __restrict__ A, int lda,
             const float* __restrict__ B, int ldb,
             float* __restrict__ C, int ldc,
             int N, int K)
{
    __shared__ __align__(16) float As[XBK][XBM];   // [k][m], m contiguous
    __shared__ __align__(16) ull   Bs[XBK][XBN];   // [k][n], (b,b) dup pairs

    const int tid = threadIdx.x;
    const int tx = tid & 15;         // n group (4 n)
    const int ty = tid >> 4;         // m group (8 m = 4 pairs)
    const int bm = blockIdx.y * XBM;
    const int bn = blockIdx.x * XBN;

    const int a_row = tid >> 1;          // 0..127
    const int a_k   = (tid & 1) * 8;     // 0/8
    const int b_row = tid >> 2;          // 0..63
    const int b_k   = (tid & 3) * 4;     // 0,4,8,12

    const float* Aptr = A + (size_t)(bm + a_row) * lda + a_k;
    const int gbn = bn + b_row;
    const float* Bptr = (gbn < N) ? (B + (size_t)gbn * ldb + b_k) : 0;

    ull acc[4][4];
    #pragma unroll
    for (int i = 0; i < 4; i++)
        #pragma unroll
        for (int j = 0; j < 4; j++) acc[i][j] = 0ull;

    const int chunks = K / XBK;

    float4 ra0 = *(const float4*)(Aptr);
    float4 ra1 = *(const float4*)(Aptr + 4);
    float4 rb  = Bptr ? *(const float4*)(Bptr) : make_float4(0.f,0.f,0.f,0.f);

    for (int c = 0; c < chunks; c++) {
        // fill stage
        As[a_k + 0][a_row] = ra0.x; As[a_k + 1][a_row] = ra0.y;
        As[a_k + 2][a_row] = ra0.z; As[a_k + 3][a_row] = ra0.w;
        As[a_k + 4][a_row] = ra1.x; As[a_k + 5][a_row] = ra1.y;
        As[a_k + 6][a_row] = ra1.z; As[a_k + 7][a_row] = ra1.w;
        Bs[b_k + 0][b_row] = f32x2_dup(rb.x);
        Bs[b_k + 1][b_row] = f32x2_dup(rb.y);
        Bs[b_k + 2][b_row] = f32x2_dup(rb.z);
        Bs[b_k + 3][b_row] = f32x2_dup(rb.w);
        __syncthreads();

        // prefetch next chunk (overlaps math below)
        if (c + 1 < chunks) {
            int ko = (c + 1) * XBK;
            ra0 = *(const float4*)(Aptr + ko);
            ra1 = *(const float4*)(Aptr + ko + 4);
            rb  = Bptr ? *(const float4*)(Bptr + ko) : make_float4(0.f,0.f,0.f,0.f);
        }

        // math: 16 kk x 16 fma.f32x2 (=512 FMA) per thread
        #pragma unroll
        for (int kk = 0; kk < XBK; kk++) {
            const ull* arow = (const ull*)As[kk];
            ull av[4], bv2[4];
            #pragma unroll
            for (int i = 0; i < 4; i++) av[i] = arow[ty * 4 + i];
            #pragma unroll
            for (int j = 0; j < 4; j++) bv2[j] = Bs[kk][tx * 4 + j];
            #pragma unroll
            for (int i = 0; i < 4; i++)
                #pragma unroll
                for (int j = 0; j < 4; j++)
                    acc[i][j] = f32x2_fma(av[i], bv2[j], acc[i][j]);
        }
        __syncthreads();
    }

    // epilogue
    #pragma unroll
    for (int i = 0; i < 4; i++) {
        int m0 = bm + ty * 8 + 2 * i;
        #pragma unroll
        for (int j = 0; j < 4; j++) {
            int n = bn + tx * 4 + j;
            if (n < N) {
                float lo, hi;
                f32x2_unpack(lo, hi, acc[i][j]);
                float* p0 = C + (size_t)m0 * ldc + n;
                float* p1 = p0 + ldc;
                if (EPI == 2) { *p0 += lo; *p1 += hi; }
                else          { *p0 = lo;  *p1 = hi;  }
            }
        }
    }
}

// ---------------- orchestration --------------------------------------------
extern "C" void kernel_launch(void* const* d_in, const int* in_sizes, int n_in,
                              void* d_out, int out_size)
{
    const int*   ids        = (const int*)  d_in[0];
    const float* emb        = (const float*)d_in[1];
    const float* in_proj_w  = (const float*)d_in[2];
    const float* conv_w     = (const float*)d_in[3];
    const float* conv_b     = (const float*)d_in[4];
    const float* x_proj_w   = (const float*)d_in[5];
    const float* dt_proj_w  = (const float*)d_in[6];
    const float* dt_proj_b  = (const float*)d_in[7];
    const float* A_log      = (const float*)d_in[8];
    const float* D_param    = (const float*)d_in[9];
    const float* out_proj_w = (const float*)d_in[10];
    const float* norm_w     = (const float*)d_in[11];
    const float* norm_f_w   = (const float*)d_in[12];
    float* logits = (float*)d_out;

    float *h, *hn, *xz, *xc, *dbl, *dt, *y;
    cudaGetSymbolAddress((void**)&h,   g_h);
    cudaGetSymbolAddress((void**)&hn,  g_hn);
    cudaGetSymbolAddress((void**)&xz,  g_xz);
    cudaGetSymbolAddress((void**)&xc,  g_xc);
    cudaGetSymbolAddress((void**)&dbl, g_dbl);
    cudaGetSymbolAddress((void**)&dt,  g_dt);
    cudaGetSymbolAddress((void**)&y,   g_y);

    embed_kernel<<<L_SEQ, DM / 4>>>(ids, emb);

    for (int i = 0; i < NLAYER; i++) {
        rmsnorm_kernel<<<L_SEQ, 256>>>(h, hn, norm_w + (size_t)i * DM);

        // xz = hn @ in_proj_w^T   (1024 x 3072, K=768)
        {
            dim3 g1(2 * DI / XBN, L_SEQ / XBM);
            gemm_x2<0><<<g1, 256>>>(hn, DM,
                                    in_proj_w + (size_t)i * 2 * DI * DM, DM,
                                    xz, 2 * DI, 2 * DI, DM);
        }

        conv_silu_kernel<<<(L_SEQ * DI) / 256, 256>>>(
            conv_w + (size_t)i * DI * DCONV, conv_b + (size_t)i * DI);

        // dbl = xc @ x_proj_w^T   (1024 x 80, K=1536)  — small, fp32
        {
            dim3 g2((DBL_W + GBN - 1) / GBN, L_SEQ / GBM);
            gemm_tn<0><<<g2, 256>>>(xc, DI,
                                    x_proj_w + (size_t)i * DBL_W * DI, DI,
                                    dbl, DBL_W, DBL_W, DI, 0);
        }

        // dt = softplus(dbl[:, :48] @ dt_proj_w^T + b)  (1024 x 1536, K=48)
        {
            dim3 g3((DI + GBN - 1) / GBN, L_SEQ / GBM);
            gemm_tn<1><<<g3, 256>>>(dbl, DBL_W,
                                    dt_proj_w + (size_t)i * DI * DTRANK, DTRANK,
                                    dt, DI, DI, DTRANK,
                                    dt_proj_b + (size_t)i * DI);
        }

        scan_kernel<<<DI / 8, 128>>>(A_log + (size_t)i * DI * DSTATE);

        y_epi_kernel<<<(L_SEQ * DI) / 256, 256>>>(D_param + (size_t)i * DI);

        // h += y @ out_proj_w^T   (1024 x 768, K=1536), residual accumulate
        {
            dim3 g4(DM / XBN, L_SEQ / XBM);
            gemm_x2<2><<<g4, 256>>>(y, DI,
                                    out_proj_w + (size_t)i * DM * DI, DI,
                                    h, DM, DM, DI);
        }
    }

    rmsnorm_kernel<<<L_SEQ, 256>>>(h, hn, norm_f_w);

    // logits = hn @ emb^T   (1024 x 50280, K=768) — dominant GEMM
    {
        dim3 g5((VOCAB + XBN - 1) / XBN, L_SEQ / XBM);
        gemm_x2<0><<<g5, 256>>>(hn, DM, emb, DM, logits, VOCAB, VOCAB, DM);
    }
}

// round 6
// speedup vs baseline: 2.0804x; 2.0804x over previous
#include <cuda_runtime.h>
#include <cuda_bf16.h>
#include <math.h>
#include <stdint.h>

#define L_SEQ 1024
#define DM 768
#define DI 1536
#define DSTATE 16
#define DCONV 4
#define DTRANK 48
#define NLAYER 4
#define VOCAB 50280
#define VOCAB_PAD 50304            // 393*128
#define DBL_W (DTRANK + 2*DSTATE)  // 80

// ---------------- scratch (device globals) ---------------------------------
__device__ float g_h [L_SEQ*DM];
__device__ float g_xz[L_SEQ*2*DI];
__device__ float g_xc[L_SEQ*DI];
__device__ float g_dbl[L_SEQ*DBL_W];
__device__ float g_dt[L_SEQ*DI];
__device__ float g_y [L_SEQ*DI];

// bf16x3 split buffers (K-concatenated: A'=[Ah|Al|Ah], B'=[Bh|Bh|Bl])
__device__ __nv_bfloat16 g_emb_s [(size_t)VOCAB_PAD * 3 * DM];
__device__ __nv_bfloat16 g_hn_s  [(size_t)L_SEQ     * 3 * DM];
__device__ __nv_bfloat16 g_inw_s [(size_t)2*DI      * 3 * DM];
__device__ __nv_bfloat16 g_y_s   [(size_t)L_SEQ     * 3 * DI];
__device__ __nv_bfloat16 g_outw_s[(size_t)DM        * 3 * DI];

__device__ __forceinline__ uint32_t s2u(const void* p){
    uint32_t a;
    asm("{ .reg .u64 t; cvta.to.shared.u64 t, %1; cvt.u32.u64 %0, t; }"
        : "=r"(a) : "l"(p));
    return a;
}

// ---------------- embedding gather ----------------------------------------
__global__ void embed_kernel(const int* __restrict__ ids,
                             const float* __restrict__ emb)
{
    int l = blockIdx.x;
    int id = ids[l];
    const float4* src = (const float4*)(emb + (size_t)id * DM);
    float4* dst = (float4*)(g_h + (size_t)l * DM);
    dst[threadIdx.x] = src[threadIdx.x];
}

// ---------------- rmsnorm + fused bf16x3 split (A-side: lo in seg 1) -------
__global__ void rmsnorm_split_kernel(const float* __restrict__ in,
                                     __nv_bfloat16* __restrict__ out_s,
                                     const float* __restrict__ w)
{
    int l = blockIdx.x;
    const float* x = in + (size_t)l * DM;
    float ss = 0.f;
    for (int i = threadIdx.x; i < DM; i += 256) {
        float v = x[i];
        ss = fmaf(v, v, ss);
    }
    #pragma unroll
    for (int off = 16; off >= 1; off >>= 1)
        ss += __shfl_xor_sync(0xffffffffu, ss, off);

    __shared__ float red[8];
    __shared__ float scale_s;
    int warp = threadIdx.x >> 5, lane = threadIdx.x & 31;
    if (lane == 0) red[warp] = ss;
    __syncthreads();
    if (threadIdx.x == 0) {
        float t = 0.f;
        #pragma unroll
        for (int i = 0; i < 8; i++) t += red[i];
        scale_s = rsqrtf(t / (float)DM + 1e-5f);
    }
    __syncthreads();
    float scale = scale_s;
    __nv_bfloat16* row = out_s + (size_t)l * 3 * DM;
    for (int i = threadIdx.x; i < DM; i += 256) {
        float v = x[i] * scale * w[i];
        __nv_bfloat16 h = __float2bfloat16(v);
        __nv_bfloat16 lo = __float2bfloat16(v - __bfloat162float(h));
        row[i]          = h;
        row[DM + i]     = lo;
        row[2 * DM + i] = h;
    }
}

// ---------------- generic bf16x3 split (weights / emb: lo in seg 2) --------
__global__ void split3_kernel(const float* __restrict__ src,
                              __nv_bfloat16* __restrict__ dst,
                              int R, int K, int Rpad, int lo_seg)
{
    long long idx = (long long)blockIdx.x * blockDim.x + threadIdx.x;
    if (idx >= (long long)Rpad * K) return;
    int r = (int)(idx / K);
    int k = (int)(idx - (long long)r * K);
    float v = (r < R) ? src[(size_t)r * K + k] : 0.f;
    __nv_bfloat16 h = __float2bfloat16(v);
    __nv_bfloat16 l = __float2bfloat16(v - __bfloat162float(h));
    __nv_bfloat16* row = dst + (size_t)r * 3 * K;
    row[k]         = h;
    row[K + k]     = (lo_seg == 1) ? l : h;
    row[2 * K + k] = (lo_seg == 2) ? l : h;
}

// ---------------- depthwise causal conv (k=4) + bias + silu ----------------
__global__ void conv_silu_kernel(const float* __restrict__ cw,
                                 const float* __restrict__ cb)
{
    int idx = blockIdx.x * blockDim.x + threadIdx.x;
    int l = idx / DI;
    int d = idx - l * DI;
    float4 wv = *(const float4*)(cw + (size_t)d * 4);
    float acc = cb[d];
    const float* wj = (const float*)&wv;
    #pragma unroll
    for (int j = 0; j < DCONV; j++) {
        int ll = l - (DCONV - 1) + j;
        if (ll >= 0) acc = fmaf(wj[j], g_xz[(size_t)ll * 2 * DI + d], acc);
    }
    acc = acc / (1.f + __expf(-acc));
    g_xc[idx] = acc;
}

// ---------------- selective scan -------------------------------------------
__global__ void scan_kernel(const float* __restrict__ A_log)
{
    int gw   = (blockIdx.x * blockDim.x + threadIdx.x) >> 5;
    int lane = threadIdx.x & 31;
    int n    = lane & 15;
    int ch   = gw * 2 + (lane >> 4);

    float Aval = -__expf(A_log[(size_t)ch * DSTATE + n]);
    float s = 0.f;
    for (int l = 0; l < L_SEQ; l++) {
        float dtv = g_dt [(size_t)l * DI + ch];
        float xcv = g_xc [(size_t)l * DI + ch];
        float Bv  = g_dbl[(size_t)l * DBL_W + DTRANK + n];
        float Cv  = g_dbl[(size_t)l * DBL_W + DTRANK + DSTATE + n];
        s = __expf(dtv * Aval) * s + dtv * Bv * xcv;
        float p = s * Cv;
        p += __shfl_xor_sync(0xffffffffu, p, 1);
        p += __shfl_xor_sync(0xffffffffu, p, 2);
        p += __shfl_xor_sync(0xffffffffu, p, 4);
        p += __shfl_xor_sync(0xffffffffu, p, 8);
        if (n == 0) g_y[(size_t)l * DI + ch] = p;
    }
}

// ---------------- y = (y + xc*D) * silu(z), fused bf16x3 split -------------
__global__ void y_epi_split_kernel(const float* __restrict__ Dp)
{
    int idx = blockIdx.x * blockDim.x + threadIdx.x;   // < L_SEQ*DI
    int l = idx / DI;
    int d = idx - l * DI;
    float z  = g_xz[(size_t)l * 2 * DI + DI + d];
    float yv = g_y[idx] + g_xc[idx] * Dp[d];
    yv *= z / (1.f + __expf(-z));
    __nv_bfloat16 h = __float2bfloat16(yv);
    __nv_bfloat16 lo = __float2bfloat16(yv - __bfloat162float(h));
    __nv_bfloat16* row = g_y_s + (size_t)l * 3 * DI;
    row[d]          = h;
    row[DI + d]     = lo;
    row[2 * DI + d] = h;
}

// ---------------- fp32 TN GEMM (small shapes: x_proj, dt_proj) -------------
#define GBM 128
#define GBN 64
#define GBK 16

template<int EPI>
__global__ __launch_bounds__(256)
void gemm_tn(const float* __restrict__ A, int lda,
             const float* __restrict__ B, int ldb,
             float* __restrict__ C, int ldc,
             int N, int K, const float* __restrict__ bias)
{
    __shared__ float As[GBK][GBM + 4];
    __shared__ float Bs[GBK][GBN + 4];

    const int bm  = blockIdx.y * GBM;
    const int bn  = blockIdx.x * GBN;
    const int tid = threadIdx.x;
    const int tx  = tid & 15;
    const int ty  = tid >> 4;
    const int a_row = tid >> 1;
    const int a_k   = (tid & 1) * 8;
    const int b_row = tid >> 2;
    const int b_k   = (tid & 3) * 4;

    float acc[8][4];
    #pragma unroll
    for (int i = 0; i < 8; i++)
        #pragma unroll
        for (int j = 0; j < 4; j++) acc[i][j] = 0.f;

    const float* Aptr = A + (size_t)(bm + a_row) * lda + a_k;
    const int gbn = bn + b_row;
    const float* Bptr = (gbn < N) ? (B + (size_t)gbn * ldb + b_k) : 0;

    for (int k0 = 0; k0 < K; k0 += GBK) {
        float4 av0 = *(const float4*)(Aptr + k0);
        float4 av1 = *(const float4*)(Aptr + k0 + 4);
        float4 bv  = Bptr ? *(const float4*)(Bptr + k0)
                          : make_float4(0.f, 0.f, 0.f, 0.f);

        As[a_k + 0][a_row] = av0.x; As[a_k + 1][a_row] = av0.y;
        As[a_k + 2][a_row] = av0.z; As[a_k + 3][a_row] = av0.w;
        As[a_k + 4][a_row] = av1.x; As[a_k + 5][a_row] = av1.y;
        As[a_k + 6][a_row] = av1.z; As[a_k + 7][a_row] = av1.w;
        Bs[b_k + 0][b_row] = bv.x;  Bs[b_k + 1][b_row] = bv.y;
        Bs[b_k + 2][b_row] = bv.z;  Bs[b_k + 3][b_row] = bv.w;
        __syncthreads();

        #pragma unroll
        for (int kk = 0; kk < GBK; kk++) {
            float ar[8], br[4];
            #pragma unroll
            for (int i = 0; i < 8; i++) ar[i] = As[kk][ty * 8 + i];
            #pragma unroll
            for (int j = 0; j < 4; j++) br[j] = Bs[kk][tx * 4 + j];
            #pragma unroll
            for (int i = 0; i < 8; i++)
                #pragma unroll
                for (int j = 0; j < 4; j++)
                    acc[i][j] = fmaf(ar[i], br[j], acc[i][j]);
        }
        __syncthreads();
    }

    #pragma unroll
    for (int i = 0; i < 8; i++) {
        int m = bm + ty * 8 + i;
        #pragma unroll
        for (int j = 0; j < 4; j++) {
            int n = bn + tx * 4 + j;
            if (n < N) {
                float v = acc[i][j];
                if (EPI == 1) {
                    v += bias[n];
                    v = fmaxf(v, 0.f) + log1pf(__expf(-fabsf(v)));
                }
                if (EPI == 2) C[(size_t)m * ldc + n] += v;
                else          C[(size_t)m * ldc + n] = v;
            }
        }
    }
}

// ---------------- bf16 HMMA GEMM (mma.sync m16n8k16), 3-stage pipeline -----
// C[m][n] = sum_k A'[m][k]*B'[n][k].  CTA tile 128x128 (grid.x = M tiles so
// concurrent CTAs share B via L2), BK=32, 8 warps (2x4), warp tile 64x32.
// Conflict-free swizzle: chunk ^= (row>>1)&3  (distinct mod-128 per 8 rows).
#define TCM 128
#define TCN 128
#define TCK 32
#define TC_STAGE (TCM*64 + TCN*64)   // 16384 B

__device__ __forceinline__ void cp_async16(uint32_t s, const void* g)
{
    asm volatile("cp.async.cg.shared.global [%0], [%1], 16;\n"
                 :: "r"(s), "l"(g));
}
__device__ __forceinline__ void cp_commit(){ asm volatile("cp.async.commit_group;\n" ::: "memory"); }
template<int N> __device__ __forceinline__ void cp_wait(){ asm volatile("cp.async.wait_group %0;\n" :: "n"(N) : "memory"); }

__device__ __forceinline__ void ldsm_x4(uint32_t* r, uint32_t addr)
{
    asm volatile("ldmatrix.sync.aligned.m8n8.x4.shared.b16 {%0,%1,%2,%3}, [%4];"
                 : "=r"(r[0]), "=r"(r[1]), "=r"(r[2]), "=r"(r[3]) : "r"(addr));
}
__device__ __forceinline__ void mma16816(float* c, const uint32_t* a, const uint32_t* b)
{
    asm volatile(
        "mma.sync.aligned.m16n8k16.row.col.f32.bf16.bf16.f32 "
        "{%0,%1,%2,%3}, {%4,%5,%6,%7}, {%8,%9}, {%0,%1,%2,%3};"
        : "+f"(c[0]), "+f"(c[1]), "+f"(c[2]), "+f"(c[3])
        : "r"(a[0]), "r"(a[1]), "r"(a[2]), "r"(a[3]), "r"(b[0]), "r"(b[1]));
}

__device__ __forceinline__ uint32_t swz(int row, int chunk){
    return (uint32_t)(row * 64 + ((chunk ^ ((row >> 1) & 3)) * 16));
}

template<int EPI>
__global__ __launch_bounds__(256)
void mma_gemm(const __nv_bfloat16* __restrict__ A,
              const __nv_bfloat16* __restrict__ B,
              float* __restrict__ C, int ldc, int N, int Kp)
{
    __shared__ __align__(16) char sm[3 * TC_STAGE];   // 48 KB
    const uint32_t sbase = s2u(sm);
    const int tid  = threadIdx.x;
    const int wid  = tid >> 5, lane = tid & 31;
    const int wm   = wid & 1;          // 64-row block
    const int wn   = wid >> 1;         // 32-col block
    const int bm   = blockIdx.x * TCM; // M fastest: share B across CTAs
    const int bn   = blockIdx.y * TCN;

    const int chunks = Kp / TCK;

    // loaders: 2 A vecs + 2 B vecs / thread / stage
    const int v0 = tid, v1 = tid + 256;
    const int ar0 = v0 >> 2, ak0 = v0 & 3;
    const int ar1 = v1 >> 2, ak1 = v1 & 3;
    const __nv_bfloat16* Ag0 = A + (size_t)(bm + ar0) * Kp + ak0 * 8;
    const __nv_bfloat16* Ag1 = A + (size_t)(bm + ar1) * Kp + ak1 * 8;
    const __nv_bfloat16* Bg0 = B + (size_t)(bn + ar0) * Kp + ak0 * 8;
    const __nv_bfloat16* Bg1 = B + (size_t)(bn + ar1) * Kp + ak1 * 8;
    const uint32_t sa0 = sbase + swz(ar0, ak0);
    const uint32_t sa1 = sbase + swz(ar1, ak1);
    const uint32_t sb0 = sbase + TCM * 64 + swz(ar0, ak0);
    const uint32_t sb1 = sbase + TCM * 64 + swz(ar1, ak1);

    float acc[4][4][4];
    #pragma unroll
    for (int i = 0; i < 4; i++)
        #pragma unroll
        for (int j = 0; j < 4; j++)
            #pragma unroll
            for (int t = 0; t < 4; t++) acc[i][j][t] = 0.f;

    const int a_row = wm * 64 + (lane & 15);
    const int a_k8s = lane >> 4;
    const int b_row = wn * 32 + (lane & 7) + ((lane >> 4) << 3);
    const int b_k8s = (lane >> 3) & 1;

    // prologue: stages 0,1
    {
        cp_async16(sa0, Ag0); cp_async16(sa1, Ag1);
        cp_async16(sb0, Bg0); cp_async16(sb1, Bg1);
        cp_commit();
        if (chunks > 1) {
            cp_async16(sa0 + TC_STAGE, Ag0 + TCK); cp_async16(sa1 + TC_STAGE, Ag1 + TCK);
            cp_async16(sb0 + TC_STAGE, Bg0 + TCK); cp_async16(sb1 + TC_STAGE, Bg1 + TCK);
            cp_commit();
        }
    }

    for (int c = 0; c < chunks; c++) {
        if (c < chunks - 1) cp_wait<1>(); else cp_wait<0>();
        __syncthreads();

        if (c + 2 < chunks) {
            const uint32_t so = ((c + 2) % 3) * TC_STAGE;
            const int ko = (c + 2) * TCK;
            cp_async16(sa0 + so, Ag0 + ko); cp_async16(sa1 + so, Ag1 + ko);
            cp_async16(sb0 + so, Bg0 + ko); cp_async16(sb1 + so, Bg1 + ko);
            cp_commit();
        }

        const uint32_t sA = sbase + (c % 3) * TC_STAGE;
        const uint32_t sB = sA + TCM * 64;

        #pragma unroll
        for (int k16 = 0; k16 < 2; k16++) {
            uint32_t afrag[4][4];
            #pragma unroll
            for (int mt = 0; mt < 4; mt++) {
                int row = a_row + mt * 16;
                ldsm_x4(afrag[mt], sA + swz(row, k16 * 2 + a_k8s));
            }
            uint32_t bfrag[4][2];
            #pragma unroll
            for (int np = 0; np < 2; np++) {
                int row = b_row + np * 16;
                uint32_t t[4];
                ldsm_x4(t, sB + swz(row, k16 * 2 + b_k8s));
                bfrag[np * 2 + 0][0] = t[0]; bfrag[np * 2 + 0][1] = t[1];
                bfrag[np * 2 + 1][0] = t[2]; bfrag[np * 2 + 1][1] = t[3];
            }
            #pragma unroll
            for (int mt = 0; mt < 4; mt++)
                #pragma unroll
                for (int nt = 0; nt < 4; nt++)
                    mma16816(acc[mt][nt], afrag[mt], bfrag[nt]);
        }
        __syncthreads();
    }

    // epilogue
    const int erow = lane >> 2;
    const int ecol = (lane & 3) * 2;
    #pragma unroll
    for (int mt = 0; mt < 4; mt++) {
        #pragma unroll
        for (int nt = 0; nt < 4; nt++) {
            int m0 = bm + wm * 64 + mt * 16 + erow;
            int n0 = bn + wn * 32 + nt * 8 + ecol;
            float* p0 = C + (size_t)m0 * ldc + n0;
            float* p1 = p0 + 8 * ldc;
            if (n0 < N) {
                float2 v0 = make_float2(acc[mt][nt][0], acc[mt][nt][1]);
                float2 v1 = make_float2(acc[mt][nt][2], acc[mt][nt][3]);
                if (EPI == 2) {
                    float2 o0 = *(float2*)p0, o1 = *(float2*)p1;
                    v0.x += o0.x; v0.y += o0.y; v1.x += o1.x; v1.y += o1.y;
                }
                *(float2*)p0 = v0;
                *(float2*)p1 = v1;
            }
        }
    }
}

// ---------------- orchestration --------------------------------------------
extern "C" void kernel_launch(void* const* d_in, const int* in_sizes, int n_in,
                              void* d_out, int out_size)
{
    const int*   ids        = (const int*)  d_in[0];
    const float* emb        = (const float*)d_in[1];
    const float* in_proj_w  = (const float*)d_in[2];
    const float* conv_w     = (const float*)d_in[3];
    const float* conv_b     = (const float*)d_in[4];
    const float* x_proj_w   = (const float*)d_in[5];
    const float* dt_proj_w  = (const float*)d_in[6];
    const float* dt_proj_b  = (const float*)d_in[7];
    const float* A_log      = (const float*)d_in[8];
    const float* D_param    = (const float*)d_in[9];
    const float* out_proj_w = (const float*)d_in[10];
    const float* norm_w     = (const float*)d_in[11];
    const float* norm_f_w   = (const float*)d_in[12];
    float* logits = (float*)d_out;

    float *h, *xz, *xc, *dbl, *dt, *y;
    cudaGetSymbolAddress((void**)&h,   g_h);
    cudaGetSymbolAddress((void**)&xz,  g_xz);
    cudaGetSymbolAddress((void**)&xc,  g_xc);
    cudaGetSymbolAddress((void**)&dbl, g_dbl);
    cudaGetSymbolAddress((void**)&dt,  g_dt);
    cudaGetSymbolAddress((void**)&y,   g_y);

    __nv_bfloat16 *emb_s, *hn_s, *inw_s, *y_s, *outw_s;
    cudaGetSymbolAddress((void**)&emb_s,  g_emb_s);
    cudaGetSymbolAddress((void**)&hn_s,   g_hn_s);
    cudaGetSymbolAddress((void**)&inw_s,  g_inw_s);
    cudaGetSymbolAddress((void**)&y_s,    g_y_s);
    cudaGetSymbolAddress((void**)&outw_s, g_outw_s);

    embed_kernel<<<L_SEQ, DM / 4>>>(ids, emb);                              // #1

    for (int i = 0; i < NLAYER; i++) {
        rmsnorm_split_kernel<<<L_SEQ, 256>>>(h, hn_s, norm_w + (size_t)i * DM);  // #2
        split3_kernel<<<(2 * DI * DM) / 256, 256>>>(in_proj_w + (size_t)i * 2 * DI * DM,
                                                    inw_s, 2 * DI, DM, 2 * DI, 2); // #3

        // xz = hn @ in_proj_w^T   (1024 x 3072, K'=2304)   <-- launch #4, profiled
        {
            dim3 g1(L_SEQ / TCM, 2 * DI / TCN);
            mma_gemm<0><<<g1, 256>>>(hn_s, inw_s, xz, 2 * DI, 2 * DI, 3 * DM);
        }

        conv_silu_kernel<<<(L_SEQ * DI) / 256, 256>>>(
            conv_w + (size_t)i * DI * DCONV, conv_b + (size_t)i * DI);

        // dbl = xc @ x_proj_w^T   (1024 x 80, K=1536)  — small, fp32
        {
            dim3 g2((DBL_W + GBN - 1) / GBN, L_SEQ / GBM);
            gemm_tn<0><<<g2, 256>>>(xc, DI,
                                    x_proj_w + (size_t)i * DBL_W * DI, DI,
                                    dbl, DBL_W, DBL_W, DI, 0);
        }

        // dt = softplus(dbl[:, :48] @ dt_proj_w^T + b)  (1024 x 1536, K=48)
        {
            dim3 g3((DI + GBN - 1) / GBN, L_SEQ / GBM);
            gemm_tn<1><<<g3, 256>>>(dbl, DBL_W,
                                    dt_proj_w + (size_t)i * DI * DTRANK, DTRANK,
                                    dt, DI, DI, DTRANK,
                                    dt_proj_b + (size_t)i * DI);
        }

        scan_kernel<<<DI / 8, 128>>>(A_log + (size_t)i * DI * DSTATE);

        y_epi_split_kernel<<<(L_SEQ * DI) / 256, 256>>>(D_param + (size_t)i * DI);

        split3_kernel<<<(DM * DI) / 256, 256>>>(out_proj_w + (size_t)i * DM * DI,
                                                outw_s, DM, DI, DM, 2);

        // h += y @ out_proj_w^T   (1024 x 768, K'=4608)
        {
            dim3 g4(L_SEQ / TCM, DM / TCN);
            mma_gemm<2><<<g4, 256>>>(y_s, outw_s, h, DM, DM, 3 * DI);
        }
    }

    rmsnorm_split_kernel<<<L_SEQ, 256>>>(h, hn_s, norm_f_w);
    {
        long long tot = (long long)VOCAB_PAD * DM;
        split3_kernel<<<(unsigned)((tot + 255) / 256), 256>>>(emb, emb_s, VOCAB, DM, VOCAB_PAD, 2);
    }

    // logits = hn @ emb^T   (1024 x 50280, K'=2304) — dominant GEMM
    {
        dim3 g5(L_SEQ / TCM, VOCAB_PAD / TCN);
        mma_gemm<0><<<g5, 256>>>(hn_s, emb_s, logits, VOCAB, VOCAB, 3 * DM);
    }
}

// round 7
// speedup vs baseline: 2.3443x; 1.1268x over previous
#include <cuda_runtime.h>
#include <cuda_bf16.h>
#include <math.h>
#include <stdint.h>

#define L_SEQ 1024
#define DM 768
#define DI 1536
#define DSTATE 16
#define DCONV 4
#define DTRANK 48
#define NLAYER 4
#define VOCAB 50280
#define VOCAB_PAD 50304            // 393*128
#define DBL_W (DTRANK + 2*DSTATE)  // 80

// ---------------- scratch (device globals) ---------------------------------
__device__ float g_h [L_SEQ*DM];
__device__ float g_xz[L_SEQ*2*DI];
__device__ float g_xc[L_SEQ*DI];
__device__ float g_dbl[L_SEQ*DBL_W];
__device__ float g_dt[L_SEQ*DI];
__device__ float g_y [L_SEQ*DI];
__device__ float g_part[3 * L_SEQ * DM];   // split-K partials for out_proj

// bf16x2-segment split buffers: row = [hi | lo], width 2K.
// GEMM iterates 3K virtual chunks: A'=[Ah|Al|Ah], B'=[Bh|Bh|Bl] via remap.
__device__ __nv_bfloat16 g_emb_s [(size_t)VOCAB_PAD * 2 * DM];
__device__ __nv_bfloat16 g_hn_s  [(size_t)L_SEQ     * 2 * DM];
__device__ __nv_bfloat16 g_inw_s [(size_t)2*DI      * 2 * DM];
__device__ __nv_bfloat16 g_y_s   [(size_t)L_SEQ     * 2 * DI];
__device__ __nv_bfloat16 g_outw_s[(size_t)DM        * 2 * DI];

__device__ __forceinline__ uint32_t s2u(const void* p){
    uint32_t a;
    asm("{ .reg .u64 t; cvta.to.shared.u64 t, %1; cvt.u32.u64 %0, t; }"
        : "=r"(a) : "l"(p));
    return a;
}

// ---------------- embedding gather ----------------------------------------
__global__ void embed_kernel(const int* __restrict__ ids,
                             const float* __restrict__ emb)
{
    int l = blockIdx.x;
    int id = ids[l];
    const float4* src = (const float4*)(emb + (size_t)id * DM);
    float4* dst = (float4*)(g_h + (size_t)l * DM);
    dst[threadIdx.x] = src[threadIdx.x];
}

// ---------------- rmsnorm + fused [h|l] split ------------------------------
__global__ void rmsnorm_split_kernel(const float* __restrict__ in,
                                     __nv_bfloat16* __restrict__ out_s,
                                     const float* __restrict__ w)
{
    int l = blockIdx.x;
    const float* x = in + (size_t)l * DM;
    float ss = 0.f;
    for (int i = threadIdx.x; i < DM; i += 256) {
        float v = x[i];
        ss = fmaf(v, v, ss);
    }
    #pragma unroll
    for (int off = 16; off >= 1; off >>= 1)
        ss += __shfl_xor_sync(0xffffffffu, ss, off);

    __shared__ float red[8];
    __shared__ float scale_s;
    int warp = threadIdx.x >> 5, lane = threadIdx.x & 31;
    if (lane == 0) red[warp] = ss;
    __syncthreads();
    if (threadIdx.x == 0) {
        float t = 0.f;
        #pragma unroll
        for (int i = 0; i < 8; i++) t += red[i];
        scale_s = rsqrtf(t / (float)DM + 1e-5f);
    }
    __syncthreads();
    float scale = scale_s;
    __nv_bfloat16* row = out_s + (size_t)l * 2 * DM;
    for (int i = threadIdx.x; i < DM; i += 256) {
        float v = x[i] * scale * w[i];
        __nv_bfloat16 h = __float2bfloat16(v);
        __nv_bfloat16 lo = __float2bfloat16(v - __bfloat162float(h));
        row[i]      = h;
        row[DM + i] = lo;
    }
}

// ---------------- generic [h|l] split --------------------------------------
__global__ void split2_kernel(const float* __restrict__ src,
                              __nv_bfloat16* __restrict__ dst,
                              int R, int K, long long total)
{
    long long idx = (long long)blockIdx.x * blockDim.x + threadIdx.x;
    if (idx >= total) return;
    int r = (int)(idx / K);
    int k = (int)(idx - (long long)r * K);
    float v = (r < R) ? src[(size_t)r * K + k] : 0.f;
    __nv_bfloat16 h = __float2bfloat16(v);
    __nv_bfloat16 l = __float2bfloat16(v - __bfloat162float(h));
    __nv_bfloat16* row = dst + (size_t)r * 2 * K;
    row[k]     = h;
    row[K + k] = l;
}

// ---------------- depthwise causal conv (k=4) + bias + silu ----------------
__global__ void conv_silu_kernel(const float* __restrict__ cw,
                                 const float* __restrict__ cb)
{
    int idx = blockIdx.x * blockDim.x + threadIdx.x;
    int l = idx / DI;
    int d = idx - l * DI;
    float4 wv = *(const float4*)(cw + (size_t)d * 4);
    float acc = cb[d];
    const float* wj = (const float*)&wv;
    #pragma unroll
    for (int j = 0; j < DCONV; j++) {
        int ll = l - (DCONV - 1) + j;
        if (ll >= 0) acc = fmaf(wj[j], g_xz[(size_t)ll * 2 * DI + d], acc);
    }
    acc = acc / (1.f + __expf(-acc));
    g_xc[idx] = acc;
}

// ---------------- selective scan -------------------------------------------
__global__ void scan_kernel(const float* __restrict__ A_log)
{
    int gw   = (blockIdx.x * blockDim.x + threadIdx.x) >> 5;
    int lane = threadIdx.x & 31;
    int n    = lane & 15;
    int ch   = gw * 2 + (lane >> 4);

    float Aval = -__expf(A_log[(size_t)ch * DSTATE + n]);
    float s = 0.f;
    for (int l = 0; l < L_SEQ; l++) {
        float dtv = g_dt [(size_t)l * DI + ch];
        float xcv = g_xc [(size_t)l * DI + ch];
        float Bv  = g_dbl[(size_t)l * DBL_W + DTRANK + n];
        float Cv  = g_dbl[(size_t)l * DBL_W + DTRANK + DSTATE + n];
        s = __expf(dtv * Aval) * s + dtv * Bv * xcv;
        float p = s * Cv;
        p += __shfl_xor_sync(0xffffffffu, p, 1);
        p += __shfl_xor_sync(0xffffffffu, p, 2);
        p += __shfl_xor_sync(0xffffffffu, p, 4);
        p += __shfl_xor_sync(0xffffffffu, p, 8);
        if (n == 0) g_y[(size_t)l * DI + ch] = p;
    }
}

// ---------------- y = (y + xc*D) * silu(z), fused [h|l] split --------------
__global__ void y_epi_split_kernel(const float* __restrict__ Dp)
{
    int idx = blockIdx.x * blockDim.x + threadIdx.x;   // < L_SEQ*DI
    int l = idx / DI;
    int d = idx - l * DI;
    float z  = g_xz[(size_t)l * 2 * DI + DI + d];
    float yv = g_y[idx] + g_xc[idx] * Dp[d];
    yv *= z / (1.f + __expf(-z));
    __nv_bfloat16 h = __float2bfloat16(yv);
    __nv_bfloat16 lo = __float2bfloat16(yv - __bfloat162float(h));
    __nv_bfloat16* row = g_y_s + (size_t)l * 2 * DI;
    row[d]      = h;
    row[DI + d] = lo;
}

// ---------------- split-K combine: h += p0 + p1 + p2 -----------------------
__global__ void combine_kernel()
{
    int idx = blockIdx.x * blockDim.x + threadIdx.x;   // < L_SEQ*DM
    const int S = L_SEQ * DM;
    g_h[idx] += g_part[idx] + g_part[idx + S] + g_part[idx + 2 * S];
}

// ---------------- fp32 TN GEMM (small shapes: x_proj, dt_proj) -------------
#define GBM 128
#define GBN 64
#define GBK 16

template<int EPI>
__global__ __launch_bounds__(256)
void gemm_tn(const float* __restrict__ A, int lda,
             const float* __restrict__ B, int ldb,
             float* __restrict__ C, int ldc,
             int N, int K, const float* __restrict__ bias)
{
    __shared__ float As[GBK][GBM + 4];
    __shared__ float Bs[GBK][GBN + 4];

    const int bm  = blockIdx.y * GBM;
    const int bn  = blockIdx.x * GBN;
    const int tid = threadIdx.x;
    const int tx  = tid & 15;
    const int ty  = tid >> 4;
    const int a_row = tid >> 1;
    const int a_k   = (tid & 1) * 8;
    const int b_row = tid >> 2;
    const int b_k   = (tid & 3) * 4;

    float acc[8][4];
    #pragma unroll
    for (int i = 0; i < 8; i++)
        #pragma unroll
        for (int j = 0; j < 4; j++) acc[i][j] = 0.f;

    const float* Aptr = A + (size_t)(bm + a_row) * lda + a_k;
    const int gbn = bn + b_row;
    const float* Bptr = (gbn < N) ? (B + (size_t)gbn * ldb + b_k) : 0;

    for (int k0 = 0; k0 < K; k0 += GBK) {
        float4 av0 = *(const float4*)(Aptr + k0);
        float4 av1 = *(const float4*)(Aptr + k0 + 4);
        float4 bv  = Bptr ? *(const float4*)(Bptr + k0)
                          : make_float4(0.f, 0.f, 0.f, 0.f);

        As[a_k + 0][a_row] = av0.x; As[a_k + 1][a_row] = av0.y;
        As[a_k + 2][a_row] = av0.z; As[a_k + 3][a_row] = av0.w;
        As[a_k + 4][a_row] = av1.x; As[a_k + 5][a_row] = av1.y;
        As[a_k + 6][a_row] = av1.z; As[a_k + 7][a_row] = av1.w;
        Bs[b_k + 0][b_row] = bv.x;  Bs[b_k + 1][b_row] = bv.y;
        Bs[b_k + 2][b_row] = bv.z;  Bs[b_k + 3][b_row] = bv.w;
        __syncthreads();

        #pragma unroll
        for (int kk = 0; kk < GBK; kk++) {
            float ar[8], br[4];
            #pragma unroll
            for (int i = 0; i < 8; i++) ar[i] = As[kk][ty * 8 + i];
            #pragma unroll
            for (int j = 0; j < 4; j++) br[j] = Bs[kk][tx * 4 + j];
            #pragma unroll
            for (int i = 0; i < 8; i++)
                #pragma unroll
                for (int j = 0; j < 4; j++)
                    acc[i][j] = fmaf(ar[i], br[j], acc[i][j]);
        }
        __syncthreads();
    }

    #pragma unroll
    for (int i = 0; i < 8; i++) {
        int m = bm + ty * 8 + i;
        #pragma unroll
        for (int j = 0; j < 4; j++) {
            int n = bn + tx * 4 + j;
            if (n < N) {
                float v = acc[i][j];
                if (EPI == 1) {
                    v += bias[n];
                    v = fmaxf(v, 0.f) + log1pf(__expf(-fabsf(v)));
                }
                C[(size_t)m * ldc + n] = v;
            }
        }
    }
}

// ---------------- bf16 HMMA GEMM, 128x64 tile, 4 warps, 3-stage ------------
// Virtual K' = 3K chunks; A stored [Ah|Al] (width 2K), B stored [Bh|Bl].
// chunk c: a_col = c<2KC ? c : c-2KC ; b_col = c<KC ? c : c-KC.
// Split-K: blockIdx.z selects chunk range [z*cps, (z+1)*cps), C += z*partStride.
#define TCM 128
#define TCN 64
#define TCK 32
#define TC_ASZ (TCM*64)              // 8192
#define TC_BSZ (TCN*64)              // 4096
#define TC_STAGE (TC_ASZ + TC_BSZ)   // 12288

__device__ __forceinline__ void cp_async16(uint32_t s, const void* g)
{
    asm volatile("cp.async.cg.shared.global [%0], [%1], 16;\n"
                 :: "r"(s), "l"(g));
}
__device__ __forceinline__ void cp_commit(){ asm volatile("cp.async.commit_group;\n" ::: "memory"); }
template<int N> __device__ __forceinline__ void cp_wait(){ asm volatile("cp.async.wait_group %0;\n" :: "n"(N) : "memory"); }

__device__ __forceinline__ void ldsm_x4(uint32_t* r, uint32_t addr)
{
    asm volatile("ldmatrix.sync.aligned.m8n8.x4.shared.b16 {%0,%1,%2,%3}, [%4];"
                 : "=r"(r[0]), "=r"(r[1]), "=r"(r[2]), "=r"(r[3]) : "r"(addr));
}
__device__ __forceinline__ void mma16816(float* c, const uint32_t* a, const uint32_t* b)
{
    asm volatile(
        "mma.sync.aligned.m16n8k16.row.col.f32.bf16.bf16.f32 "
        "{%0,%1,%2,%3}, {%4,%5,%6,%7}, {%8,%9}, {%0,%1,%2,%3};"
        : "+f"(c[0]), "+f"(c[1]), "+f"(c[2]), "+f"(c[3])
        : "r"(a[0]), "r"(a[1]), "r"(a[2]), "r"(a[3]), "r"(b[0]), "r"(b[1]));
}

__device__ __forceinline__ uint32_t swz(int row, int chunk){
    return (uint32_t)(row * 64 + ((chunk ^ ((row >> 1) & 3)) * 16));
}

__global__ __launch_bounds__(128, 4)
void mma_gemm(const __nv_bfloat16* __restrict__ A,
              const __nv_bfloat16* __restrict__ B,
              float* __restrict__ C, int ldc, int N, int Kreal,
              int cps, long long partStride)
{
    __shared__ __align__(16) char sm[3 * TC_STAGE];   // 36 KB
    const uint32_t sbase = s2u(sm);
    const int tid  = threadIdx.x;
    const int wid  = tid >> 5, lane = tid & 31;
    const int wm   = wid & 1;          // 64-row block
    const int wn   = wid >> 1;         // 32-col block
    const int bm   = blockIdx.x * TCM; // M fastest: share B via L2
    const int bn   = blockIdx.y * TCN;
    const int KC   = Kreal / TCK;
    const int c0   = blockIdx.z * cps;
    const int c1   = c0 + cps;
    C += (long long)blockIdx.z * partStride;

    const int lda = 2 * Kreal;

    // loaders: A 512 vecs (4/thread), B 256 vecs (2/thread)
    const int ar0 = (tid + 0*128) >> 2,  ak0 = (tid + 0*128) & 3;
    const int ar1 = (tid + 1*128) >> 2,  ak1 = (tid + 1*128) & 3;
    const int ar2 = (tid + 2*128) >> 2,  ak2 = (tid + 2*128) & 3;
    const int ar3 = (tid + 3*128) >> 2,  ak3 = (tid + 3*128) & 3;
    const __nv_bfloat16* Ag0 = A + (size_t)(bm + ar0) * lda + ak0 * 8;
    const __nv_bfloat16* Ag1 = A + (size_t)(bm + ar1) * lda + ak1 * 8;
    const __nv_bfloat16* Ag2 = A + (size_t)(bm + ar2) * lda + ak2 * 8;
    const __nv_bfloat16* Ag3 = A + (size_t)(bm + ar3) * lda + ak3 * 8;
    const __nv_bfloat16* Bg0 = B + (size_t)(bn + ar0) * lda + ak0 * 8;
    const __nv_bfloat16* Bg1 = B + (size_t)(bn + ar1) * lda + ak1 * 8;
    const uint32_t sa0 = sbase + swz(ar0, ak0);
    const uint32_t sa1 = sbase + swz(ar1, ak1);
    const uint32_t sa2 = sbase + swz(ar2, ak2);
    const uint32_t sa3 = sbase + swz(ar3, ak3);
    const uint32_t sb0 = sbase + TC_ASZ + swz(ar0, ak0);
    const uint32_t sb1 = sbase + TC_ASZ + swz(ar1, ak1);

    float acc[4][4][4];
    #pragma unroll
    for (int i = 0; i < 4; i++)
        #pragma unroll
        for (int j = 0; j < 4; j++)
            #pragma unroll
            for (int t = 0; t < 4; t++) acc[i][j][t] = 0.f;

    const int a_row = wm * 64 + (lane & 15);
    const int a_k8s = lane >> 4;
    const int b_row = wn * 32 + (lane & 7) + ((lane >> 4) << 3);
    const int b_k8s = (lane >> 3) & 1;

    #define LOAD_STAGE(cc, so) do { \
        int ac = ((cc) < 2*KC ? (cc) : (cc) - 2*KC) * TCK; \
        int bc = ((cc) < KC   ? (cc) : (cc) - KC)   * TCK; \
        cp_async16(sa0 + (so), Ag0 + ac); cp_async16(sa1 + (so), Ag1 + ac); \
        cp_async16(sa2 + (so), Ag2 + ac); cp_async16(sa3 + (so), Ag3 + ac); \
        cp_async16(sb0 + (so), Bg0 + bc); cp_async16(sb1 + (so), Bg1 + bc); \
        cp_commit(); \
    } while (0)

    LOAD_STAGE(c0, 0);
    if (c1 - c0 > 1) LOAD_STAGE(c0 + 1, TC_STAGE);

    for (int c = c0; c < c1; c++) {
        if (c < c1 - 1) cp_wait<1>(); else cp_wait<0>();
        __syncthreads();

        if (c + 2 < c1) {
            const uint32_t so = (uint32_t)(((c + 2 - c0) % 3) * TC_STAGE);
            LOAD_STAGE(c + 2, so);
        }

        const uint32_t sA = sbase + ((c - c0) % 3) * TC_STAGE;
        const uint32_t sB = sA + TC_ASZ;

        #pragma unroll
        for (int k16 = 0; k16 < 2; k16++) {
            uint32_t afrag[4][4];
            #pragma unroll
            for (int mt = 0; mt < 4; mt++) {
                int row = a_row + mt * 16;
                ldsm_x4(afrag[mt], sA + swz(row, k16 * 2 + a_k8s));
            }
            uint32_t bfrag[4][2];
            #pragma unroll
            for (int np = 0; np < 2; np++) {
                int row = b_row + np * 16;
                uint32_t t[4];
                ldsm_x4(t, sB + swz(row, k16 * 2 + b_k8s));
                bfrag[np * 2 + 0][0] = t[0]; bfrag[np * 2 + 0][1] = t[1];
                bfrag[np * 2 + 1][0] = t[2]; bfrag[np * 2 + 1][1] = t[3];
            }
            #pragma unroll
            for (int mt = 0; mt < 4; mt++)
                #pragma unroll
                for (int nt = 0; nt < 4; nt++)
                    mma16816(acc[mt][nt], afrag[mt], bfrag[nt]);
        }
        __syncthreads();
    }
    #undef LOAD_STAGE

    // epilogue
    const int erow = lane >> 2;
    const int ecol = (lane & 3) * 2;
    #pragma unroll
    for (int mt = 0; mt < 4; mt++) {
        #pragma unroll
        for (int nt = 0; nt < 4; nt++) {
            int m0 = bm + wm * 64 + mt * 16 + erow;
            int n0 = bn + wn * 32 + nt * 8 + ecol;
            if (n0 < N) {
                float* p0 = C + (size_t)m0 * ldc + n0;
                float* p1 = p0 + 8 * ldc;
                *(float2*)p0 = make_float2(acc[mt][nt][0], acc[mt][nt][1]);
                *(float2*)p1 = make_float2(acc[mt][nt][2], acc[mt][nt][3]);
            }
        }
    }
}

// ---------------- orchestration --------------------------------------------
extern "C" void kernel_launch(void* const* d_in, const int* in_sizes, int n_in,
                              void* d_out, int out_size)
{
    const int*   ids        = (const int*)  d_in[0];
    const float* emb        = (const float*)d_in[1];
    const float* in_proj_w  = (const float*)d_in[2];
    const float* conv_w     = (const float*)d_in[3];
    const float* conv_b     = (const float*)d_in[4];
    const float* x_proj_w   = (const float*)d_in[5];
    const float* dt_proj_w  = (const float*)d_in[6];
    const float* dt_proj_b  = (const float*)d_in[7];
    const float* A_log      = (const float*)d_in[8];
    const float* D_param    = (const float*)d_in[9];
    const float* out_proj_w = (const float*)d_in[10];
    const float* norm_w     = (const float*)d_in[11];
    const float* norm_f_w   = (const float*)d_in[12];
    float* logits = (float*)d_out;

    float *h, *xz, *xc, *dbl, *dt, *y, *part;
    cudaGetSymbolAddress((void**)&h,    g_h);
    cudaGetSymbolAddress((void**)&xz,   g_xz);
    cudaGetSymbolAddress((void**)&xc,   g_xc);
    cudaGetSymbolAddress((void**)&dbl,  g_dbl);
    cudaGetSymbolAddress((void**)&dt,   g_dt);
    cudaGetSymbolAddress((void**)&y,    g_y);
    cudaGetSymbolAddress((void**)&part, g_part);

    __nv_bfloat16 *emb_s, *hn_s, *inw_s, *y_s, *outw_s;
    cudaGetSymbolAddress((void**)&emb_s,  g_emb_s);
    cudaGetSymbolAddress((void**)&hn_s,   g_hn_s);
    cudaGetSymbolAddress((void**)&inw_s,  g_inw_s);
    cudaGetSymbolAddress((void**)&y_s,    g_y_s);
    cudaGetSymbolAddress((void**)&outw_s, g_outw_s);

    embed_kernel<<<L_SEQ, DM / 4>>>(ids, emb);

    for (int i = 0; i < NLAYER; i++) {
        rmsnorm_split_kernel<<<L_SEQ, 256>>>(h, hn_s, norm_w + (size_t)i * DM);
        split2_kernel<<<(2 * DI * DM) / 256, 256>>>(in_proj_w + (size_t)i * 2 * DI * DM,
                                                    inw_s, 2 * DI, DM,
                                                    (long long)2 * DI * DM);

        // xz = hn @ in_proj_w^T   (1024 x 3072, K=768, K'=72 chunks)
        {
            dim3 g1(L_SEQ / TCM, 2 * DI / TCN, 1);
            mma_gemm<<<g1, 128>>>(hn_s, inw_s, xz, 2 * DI, 2 * DI, DM,
                                  3 * (DM / TCK), 0);
        }

        conv_silu_kernel<<<(L_SEQ * DI) / 256, 256>>>(
            conv_w + (size_t)i * DI * DCONV, conv_b + (size_t)i * DI);

        // dbl = xc @ x_proj_w^T   (1024 x 80, K=1536)  — small, fp32
        {
            dim3 g2((DBL_W + GBN - 1) / GBN, L_SEQ / GBM);
            gemm_tn<0><<<g2, 256>>>(xc, DI,
                                    x_proj_w + (size_t)i * DBL_W * DI, DI,
                                    dbl, DBL_W, DBL_W, DI, 0);
        }

        // dt = softplus(dbl[:, :48] @ dt_proj_w^T + b)  (1024 x 1536, K=48)
        {
            dim3 g3((DI + GBN - 1) / GBN, L_SEQ / GBM);
            gemm_tn<1><<<g3, 256>>>(dbl, DBL_W,
                                    dt_proj_w + (size_t)i * DI * DTRANK, DTRANK,
                                    dt, DI, DI, DTRANK,
                                    dt_proj_b + (size_t)i * DI);
        }

        scan_kernel<<<DI / 8, 128>>>(A_log + (size_t)i * DI * DSTATE);

        y_epi_split_kernel<<<(L_SEQ * DI) / 256, 256>>>(D_param + (size_t)i * DI);

        split2_kernel<<<(DM * DI) / 256, 256>>>(out_proj_w + (size_t)i * DM * DI,
                                                outw_s, DM, DI,
                                                (long long)DM * DI);

        // part[z] = y @ out_proj_w^T segment z   (split-K=3 over K'=144 chunks)
        {
            dim3 g4(L_SEQ / TCM, DM / TCN, 3);
            mma_gemm<<<g4, 128>>>(y_s, outw_s, part, DM, DM, DI,
                                  DI / TCK, (long long)L_SEQ * DM);
        }
        combine_kernel<<<(L_SEQ * DM) / 256, 256>>>();   // h += p0+p1+p2
    }

    rmsnorm_split_kernel<<<L_SEQ, 256>>>(h, hn_s, norm_f_w);
    {
        long long tot = (long long)VOCAB_PAD * DM;
        split2_kernel<<<(unsigned)((tot + 255) / 256), 256>>>(emb, emb_s, VOCAB, DM, tot);
    }

    // logits = hn @ emb^T   (1024 x 50280, K=768) — dominant GEMM
    {
        dim3 g5(L_SEQ / TCM, VOCAB_PAD / TCN, 1);
        mma_gemm<<<g5, 128>>>(hn_s, emb_s, logits, VOCAB, VOCAB, DM,
                              3 * (DM / TCK), 0);
    }
}

// round 8
// speedup vs baseline: 2.3538x; 1.0041x over previous
#include <cuda_runtime.h>
#include <cuda_bf16.h>
#include <math.h>
#include <stdint.h>

#define L_SEQ 1024
#define DM 768
#define DI 1536
#define DSTATE 16
#define DCONV 4
#define DTRANK 48
#define NLAYER 4
#define VOCAB 50280
#define VOCAB_PAD 50304            // 393*128
#define DBL_W (DTRANK + 2*DSTATE)  // 80

// ---------------- scratch (device globals) ---------------------------------
__device__ float g_h [L_SEQ*DM];
__device__ float g_xz[L_SEQ*2*DI];
__device__ float g_xc[L_SEQ*DI];
__device__ float g_dbl[L_SEQ*DBL_W];
__device__ float g_dt[L_SEQ*DI];
__device__ float g_y [L_SEQ*DI];
__device__ float g_part[6 * L_SEQ * DM];   // split-K partials for out_proj

// bf16 2-segment split buffers: row = [hi | lo], width 2K.
// GEMM iterates 3K virtual chunks: A'=[Ah|Al|Ah], B'=[Bh|Bh|Bl] via remap.
__device__ __nv_bfloat16 g_emb_s [(size_t)VOCAB_PAD * 2 * DM];
__device__ __nv_bfloat16 g_hn_s  [(size_t)L_SEQ     * 2 * DM];
__device__ __nv_bfloat16 g_inw_s [(size_t)2*DI      * 2 * DM];
__device__ __nv_bfloat16 g_y_s   [(size_t)L_SEQ     * 2 * DI];
__device__ __nv_bfloat16 g_outw_s[(size_t)DM        * 2 * DI];

__device__ __forceinline__ uint32_t s2u(const void* p){
    uint32_t a;
    asm("{ .reg .u64 t; cvta.to.shared.u64 t, %1; cvt.u32.u64 %0, t; }"
        : "=r"(a) : "l"(p));
    return a;
}

// ---------------- embedding gather ----------------------------------------
__global__ void embed_kernel(const int* __restrict__ ids,
                             const float* __restrict__ emb)
{
    int l = blockIdx.x;
    int id = ids[l];
    const float4* src = (const float4*)(emb + (size_t)id * DM);
    float4* dst = (float4*)(g_h + (size_t)l * DM);
    dst[threadIdx.x] = src[threadIdx.x];
}

// ---------------- rmsnorm + fused [h|l] split ------------------------------
__global__ void rmsnorm_split_kernel(const float* __restrict__ in,
                                     __nv_bfloat16* __restrict__ out_s,
                                     const float* __restrict__ w)
{
    int l = blockIdx.x;
    const float* x = in + (size_t)l * DM;
    float ss = 0.f;
    for (int i = threadIdx.x; i < DM; i += 256) {
        float v = x[i];
        ss = fmaf(v, v, ss);
    }
    #pragma unroll
    for (int off = 16; off >= 1; off >>= 1)
        ss += __shfl_xor_sync(0xffffffffu, ss, off);

    __shared__ float red[8];
    __shared__ float scale_s;
    int warp = threadIdx.x >> 5, lane = threadIdx.x & 31;
    if (lane == 0) red[warp] = ss;
    __syncthreads();
    if (threadIdx.x == 0) {
        float t = 0.f;
        #pragma unroll
        for (int i = 0; i < 8; i++) t += red[i];
        scale_s = rsqrtf(t / (float)DM + 1e-5f);
    }
    __syncthreads();
    float scale = scale_s;
    __nv_bfloat16* row = out_s + (size_t)l * 2 * DM;
    for (int i = threadIdx.x; i < DM; i += 256) {
        float v = x[i] * scale * w[i];
        __nv_bfloat16 h = __float2bfloat16(v);
        __nv_bfloat16 lo = __float2bfloat16(v - __bfloat162float(h));
        row[i]      = h;
        row[DM + i] = lo;
    }
}

// ---------------- generic [h|l] split --------------------------------------
__global__ void split2_kernel(const float* __restrict__ src,
                              __nv_bfloat16* __restrict__ dst,
                              int R, int K, long long total)
{
    long long idx = (long long)blockIdx.x * blockDim.x + threadIdx.x;
    if (idx >= total) return;
    int r = (int)(idx / K);
    int k = (int)(idx - (long long)r * K);
    float v = (r < R) ? src[(size_t)r * K + k] : 0.f;
    __nv_bfloat16 h = __float2bfloat16(v);
    __nv_bfloat16 l = __float2bfloat16(v - __bfloat162float(h));
    __nv_bfloat16* row = dst + (size_t)r * 2 * K;
    row[k]     = h;
    row[K + k] = l;
}

// ---------------- depthwise causal conv (k=4) + bias + silu ----------------
__global__ void conv_silu_kernel(const float* __restrict__ cw,
                                 const float* __restrict__ cb)
{
    int idx = blockIdx.x * blockDim.x + threadIdx.x;
    int l = idx / DI;
    int d = idx - l * DI;
    float4 wv = *(const float4*)(cw + (size_t)d * 4);
    float acc = cb[d];
    const float* wj = (const float*)&wv;
    #pragma unroll
    for (int j = 0; j < DCONV; j++) {
        int ll = l - (DCONV - 1) + j;
        if (ll >= 0) acc = fmaf(wj[j], g_xz[(size_t)ll * 2 * DI + d], acc);
    }
    acc = acc / (1.f + __expf(-acc));
    g_xc[idx] = acc;
}

// ---------------- selective scan -------------------------------------------
__global__ void scan_kernel(const float* __restrict__ A_log)
{
    int gw   = (blockIdx.x * blockDim.x + threadIdx.x) >> 5;
    int lane = threadIdx.x & 31;
    int n    = lane & 15;
    int ch   = gw * 2 + (lane >> 4);

    float Aval = -__expf(A_log[(size_t)ch * DSTATE + n]);
    float s = 0.f;
    for (int l = 0; l < L_SEQ; l++) {
        float dtv = g_dt [(size_t)l * DI + ch];
        float xcv = g_xc [(size_t)l * DI + ch];
        float Bv  = g_dbl[(size_t)l * DBL_W + DTRANK + n];
        float Cv  = g_dbl[(size_t)l * DBL_W + DTRANK + DSTATE + n];
        s = __expf(dtv * Aval) * s + dtv * Bv * xcv;
        float p = s * Cv;
        p += __shfl_xor_sync(0xffffffffu, p, 1);
        p += __shfl_xor_sync(0xffffffffu, p, 2);
        p += __shfl_xor_sync(0xffffffffu, p, 4);
        p += __shfl_xor_sync(0xffffffffu, p, 8);
        if (n == 0) g_y[(size_t)l * DI + ch] = p;
    }
}

// ---------------- y = (y + xc*D) * silu(z), fused [h|l] split --------------
__global__ void y_epi_split_kernel(const float* __restrict__ Dp)
{
    int idx = blockIdx.x * blockDim.x + threadIdx.x;   // < L_SEQ*DI
    int l = idx / DI;
    int d = idx - l * DI;
    float z  = g_xz[(size_t)l * 2 * DI + DI + d];
    float yv = g_y[idx] + g_xc[idx] * Dp[d];
    yv *= z / (1.f + __expf(-z));
    __nv_bfloat16 h = __float2bfloat16(yv);
    __nv_bfloat16 lo = __float2bfloat16(yv - __bfloat162float(h));
    __nv_bfloat16* row = g_y_s + (size_t)l * 2 * DI;
    row[d]      = h;
    row[DI + d] = lo;
}

// ---------------- split-K combine: h += sum of 6 partials ------------------
__global__ void combine_kernel()
{
    int idx = blockIdx.x * blockDim.x + threadIdx.x;   // < L_SEQ*DM
    const int S = L_SEQ * DM;
    float a = g_part[idx]         + g_part[idx + S]     + g_part[idx + 2 * S];
    float b = g_part[idx + 3 * S] + g_part[idx + 4 * S] + g_part[idx + 5 * S];
    g_h[idx] += a + b;
}

// ---------------- fp32 TN GEMM (small shapes: x_proj, dt_proj) -------------
#define GBM 128
#define GBN 64
#define GBK 16

template<int EPI>
__global__ __launch_bounds__(256)
void gemm_tn(const float* __restrict__ A, int lda,
             const float* __restrict__ B, int ldb,
             float* __restrict__ C, int ldc,
             int N, int K, const float* __restrict__ bias)
{
    __shared__ float As[GBK][GBM + 4];
    __shared__ float Bs[GBK][GBN + 4];

    const int bm  = blockIdx.y * GBM;
    const int bn  = blockIdx.x * GBN;
    const int tid = threadIdx.x;
    const int tx  = tid & 15;
    const int ty  = tid >> 4;
    const int a_row = tid >> 1;
    const int a_k   = (tid & 1) * 8;
    const int b_row = tid >> 2;
    const int b_k   = (tid & 3) * 4;

    float acc[8][4];
    #pragma unroll
    for (int i = 0; i < 8; i++)
        #pragma unroll
        for (int j = 0; j < 4; j++) acc[i][j] = 0.f;

    const float* Aptr = A + (size_t)(bm + a_row) * lda + a_k;
    const int gbn = bn + b_row;
    const float* Bptr = (gbn < N) ? (B + (size_t)gbn * ldb + b_k) : 0;

    for (int k0 = 0; k0 < K; k0 += GBK) {
        float4 av0 = *(const float4*)(Aptr + k0);
        float4 av1 = *(const float4*)(Aptr + k0 + 4);
        float4 bv  = Bptr ? *(const float4*)(Bptr + k0)
                          : make_float4(0.f, 0.f, 0.f, 0.f);

        As[a_k + 0][a_row] = av0.x; As[a_k + 1][a_row] = av0.y;
        As[a_k + 2][a_row] = av0.z; As[a_k + 3][a_row] = av0.w;
        As[a_k + 4][a_row] = av1.x; As[a_k + 5][a_row] = av1.y;
        As[a_k + 6][a_row] = av1.z; As[a_k + 7][a_row] = av1.w;
        Bs[b_k + 0][b_row] = bv.x;  Bs[b_k + 1][b_row] = bv.y;
        Bs[b_k + 2][b_row] = bv.z;  Bs[b_k + 3][b_row] = bv.w;
        __syncthreads();

        #pragma unroll
        for (int kk = 0; kk < GBK; kk++) {
            float ar[8], br[4];
            #pragma unroll
            for (int i = 0; i < 8; i++) ar[i] = As[kk][ty * 8 + i];
            #pragma unroll
            for (int j = 0; j < 4; j++) br[j] = Bs[kk][tx * 4 + j];
            #pragma unroll
            for (int i = 0; i < 8; i++)
                #pragma unroll
                for (int j = 0; j < 4; j++)
                    acc[i][j] = fmaf(ar[i], br[j], acc[i][j]);
        }
        __syncthreads();
    }

    #pragma unroll
    for (int i = 0; i < 8; i++) {
        int m = bm + ty * 8 + i;
        #pragma unroll
        for (int j = 0; j < 4; j++) {
            int n = bn + tx * 4 + j;
            if (n < N) {
                float v = acc[i][j];
                if (EPI == 1) {
                    v += bias[n];
                    v = fmaxf(v, 0.f) + log1pf(__expf(-fabsf(v)));
                }
                C[(size_t)m * ldc + n] = v;
            }
        }
    }
}

// ---------------- bf16 HMMA GEMM, 128x64 tile, 4 warps, 3-stage ------------
// Single barrier per K-chunk; stage reuse ordered by that barrier.
#define TCM 128
#define TCN 64
#define TCK 32
#define TC_ASZ (TCM*64)
#define TC_BSZ (TCN*64)
#define TC_STAGE (TC_ASZ + TC_BSZ)   // 12288

__device__ __forceinline__ void cp_async16(uint32_t s, const void* g)
{
    asm volatile("cp.async.cg.shared.global [%0], [%1], 16;\n"
                 :: "r"(s), "l"(g));
}
__device__ __forceinline__ void cp_commit(){ asm volatile("cp.async.commit_group;\n" ::: "memory"); }
template<int N> __device__ __forceinline__ void cp_wait(){ asm volatile("cp.async.wait_group %0;\n" :: "n"(N) : "memory"); }

__device__ __forceinline__ void ldsm_x4(uint32_t* r, uint32_t addr)
{
    asm volatile("ldmatrix.sync.aligned.m8n8.x4.shared.b16 {%0,%1,%2,%3}, [%4];"
                 : "=r"(r[0]), "=r"(r[1]), "=r"(r[2]), "=r"(r[3]) : "r"(addr));
}
__device__ __forceinline__ void mma16816(float* c, const uint32_t* a, const uint32_t* b)
{
    asm volatile(
        "mma.sync.aligned.m16n8k16.row.col.f32.bf16.bf16.f32 "
        "{%0,%1,%2,%3}, {%4,%5,%6,%7}, {%8,%9}, {%0,%1,%2,%3};"
        : "+f"(c[0]), "+f"(c[1]), "+f"(c[2]), "+f"(c[3])
        : "r"(a[0]), "r"(a[1]), "r"(a[2]), "r"(a[3]), "r"(b[0]), "r"(b[1]));
}

__device__ __forceinline__ uint32_t swz(int row, int chunk){
    return (uint32_t)(row * 64 + ((chunk ^ ((row >> 1) & 3)) * 16));
}

__global__ __launch_bounds__(128, 4)
void mma_gemm(const __nv_bfloat16* __restrict__ A,
              const __nv_bfloat16* __restrict__ B,
              float* __restrict__ C, int ldc, int N, int Kreal,
              int cps, long long partStride)
{
    __shared__ __align__(16) char sm[3 * TC_STAGE];   // 36 KB
    const uint32_t sbase = s2u(sm);
    const int tid  = threadIdx.x;
    const int wid  = tid >> 5, lane = tid & 31;
    const int wm   = wid & 1;
    const int wn   = wid >> 1;
    const int bm   = blockIdx.x * TCM;
    const int bn   = blockIdx.y * TCN;
    const int KC   = Kreal / TCK;
    const int c0   = blockIdx.z * cps;
    const int c1   = c0 + cps;
    C += (long long)blockIdx.z * partStride;

    const int lda = 2 * Kreal;

    const int ar0 = (tid + 0*128) >> 2,  ak0 = (tid + 0*128) & 3;
    const int ar1 = (tid + 1*128) >> 2,  ak1 = (tid + 1*128) & 3;
    const int ar2 = (tid + 2*128) >> 2,  ak2 = (tid + 2*128) & 3;
    const int ar3 = (tid + 3*128) >> 2,  ak3 = (tid + 3*128) & 3;
    const __nv_bfloat16* Ag0 = A + (size_t)(bm + ar0) * lda + ak0 * 8;
    const __nv_bfloat16* Ag1 = A + (size_t)(bm + ar1) * lda + ak1 * 8;
    const __nv_bfloat16* Ag2 = A + (size_t)(bm + ar2) * lda + ak2 * 8;
    const __nv_bfloat16* Ag3 = A + (size_t)(bm + ar3) * lda + ak3 * 8;
    const __nv_bfloat16* Bg0 = B + (size_t)(bn + ar0) * lda + ak0 * 8;
    const __nv_bfloat16* Bg1 = B + (size_t)(bn + ar1) * lda + ak1 * 8;
    const uint32_t sa0 = sbase + swz(ar0, ak0);
    const uint32_t sa1 = sbase + swz(ar1, ak1);
    const uint32_t sa2 = sbase + swz(ar2, ak2);
    const uint32_t sa3 = sbase + swz(ar3, ak3);
    const uint32_t sb0 = sbase + TC_ASZ + swz(ar0, ak0);
    const uint32_t sb1 = sbase + TC_ASZ + swz(ar1, ak1);

    float acc[4][4][4];
    #pragma unroll
    for (int i = 0; i < 4; i++)
        #pragma unroll
        for (int j = 0; j < 4; j++)
            #pragma unroll
            for (int t = 0; t < 4; t++) acc[i][j][t] = 0.f;

    const int a_row = wm * 64 + (lane & 15);
    const int a_k8s = lane >> 4;
    const int b_row = wn * 32 + (lane & 7) + ((lane >> 4) << 3);
    const int b_k8s = (lane >> 3) & 1;

    #define LOAD_STAGE(cc, so) do { \
        int ac = ((cc) < 2*KC ? (cc) : (cc) - 2*KC) * TCK; \
        int bc = ((cc) < KC   ? (cc) : (cc) - KC)   * TCK; \
        cp_async16(sa0 + (so), Ag0 + ac); cp_async16(sa1 + (so), Ag1 + ac); \
        cp_async16(sa2 + (so), Ag2 + ac); cp_async16(sa3 + (so), Ag3 + ac); \
        cp_async16(sb0 + (so), Bg0 + bc); cp_async16(sb1 + (so), Bg1 + bc); \
        cp_commit(); \
    } while (0)

    LOAD_STAGE(c0, 0);
    if (c1 - c0 > 1) LOAD_STAGE(c0 + 1, TC_STAGE);

    for (int c = c0; c < c1; c++) {
        if (c < c1 - 1) cp_wait<1>(); else cp_wait<0>();
        __syncthreads();   // data ready for stage c AND all math on stage (c%3) done

        if (c + 2 < c1) {
            const uint32_t so = (uint32_t)(((c + 2 - c0) % 3) * TC_STAGE);
            LOAD_STAGE(c + 2, so);
        }

        const uint32_t sA = sbase + ((c - c0) % 3) * TC_STAGE;
        const uint32_t sB = sA + TC_ASZ;

        #pragma unroll
        for (int k16 = 0; k16 < 2; k16++) {
            uint32_t afrag[4][4];
            #pragma unroll
            for (int mt = 0; mt < 4; mt++) {
                int row = a_row + mt * 16;
                ldsm_x4(afrag[mt], sA + swz(row, k16 * 2 + a_k8s));
            }
            uint32_t bfrag[4][2];
            #pragma unroll
            for (int np = 0; np < 2; np++) {
                int row = b_row + np * 16;
                uint32_t t[4];
                ldsm_x4(t, sB + swz(row, k16 * 2 + b_k8s));
                bfrag[np * 2 + 0][0] = t[0]; bfrag[np * 2 + 0][1] = t[1];
                bfrag[np * 2 + 1][0] = t[2]; bfrag[np * 2 + 1][1] = t[3];
            }
            #pragma unroll
            for (int mt = 0; mt < 4; mt++)
                #pragma unroll
                for (int nt = 0; nt < 4; nt++)
                    mma16816(acc[mt][nt], afrag[mt], bfrag[nt]);
        }
        // no trailing barrier: next iteration's top barrier orders stage reuse
    }
    #undef LOAD_STAGE

    const int erow = lane >> 2;
    const int ecol = (lane & 3) * 2;
    #pragma unroll
    for (int mt = 0; mt < 4; mt++) {
        #pragma unroll
        for (int nt = 0; nt < 4; nt++) {
            int m0 = bm + wm * 64 + mt * 16 + erow;
            int n0 = bn + wn * 32 + nt * 8 + ecol;
            if (n0 < N) {
                float* p0 = C + (size_t)m0 * ldc + n0;
                float* p1 = p0 + 8 * ldc;
                *(float2*)p0 = make_float2(acc[mt][nt][0], acc[mt][nt][1]);
                *(float2*)p1 = make_float2(acc[mt][nt][2], acc[mt][nt][3]);
            }
        }
    }
}

// ---------------- orchestration --------------------------------------------
extern "C" void kernel_launch(void* const* d_in, const int* in_sizes, int n_in,
                              void* d_out, int out_size)
{
    const int*   ids        = (const int*)  d_in[0];
    const float* emb        = (const float*)d_in[1];
    const float* in_proj_w  = (const float*)d_in[2];
    const float* conv_w     = (const float*)d_in[3];
    const float* conv_b     = (const float*)d_in[4];
    const float* x_proj_w   = (const float*)d_in[5];
    const float* dt_proj_w  = (const float*)d_in[6];
    const float* dt_proj_b  = (const float*)d_in[7];
    const float* A_log      = (const float*)d_in[8];
    const float* D_param    = (const float*)d_in[9];
    const float* out_proj_w = (const float*)d_in[10];
    const float* norm_w     = (const float*)d_in[11];
    const float* norm_f_w   = (const float*)d_in[12];
    float* logits = (float*)d_out;

    float *h, *xz, *xc, *dbl, *dt, *y, *part;
    cudaGetSymbolAddress((void**)&h,    g_h);
    cudaGetSymbolAddress((void**)&xz,   g_xz);
    cudaGetSymbolAddress((void**)&xc,   g_xc);
    cudaGetSymbolAddress((void**)&dbl,  g_dbl);
    cudaGetSymbolAddress((void**)&dt,   g_dt);
    cudaGetSymbolAddress((void**)&y,    g_y);
    cudaGetSymbolAddress((void**)&part, g_part);

    __nv_bfloat16 *emb_s, *hn_s, *inw_s, *y_s, *outw_s;
    cudaGetSymbolAddress((void**)&emb_s,  g_emb_s);
    cudaGetSymbolAddress((void**)&hn_s,   g_hn_s);
    cudaGetSymbolAddress((void**)&inw_s,  g_inw_s);
    cudaGetSymbolAddress((void**)&y_s,    g_y_s);
    cudaGetSymbolAddress((void**)&outw_s, g_outw_s);

    embed_kernel<<<L_SEQ, DM / 4>>>(ids, emb);

    for (int i = 0; i < NLAYER; i++) {
        rmsnorm_split_kernel<<<L_SEQ, 256>>>(h, hn_s, norm_w + (size_t)i * DM);
        split2_kernel<<<(2 * DI * DM) / 256, 256>>>(in_proj_w + (size_t)i * 2 * DI * DM,
                                                    inw_s, 2 * DI, DM,
                                                    (long long)2 * DI * DM);

        // xz = hn @ in_proj_w^T   (1024 x 3072, K=768, 72 virtual chunks)
        {
            dim3 g1(L_SEQ / TCM, 2 * DI / TCN, 1);
            mma_gemm<<<g1, 128>>>(hn_s, inw_s, xz, 2 * DI, 2 * DI, DM,
                                  3 * (DM / TCK), 0);
        }

        conv_silu_kernel<<<(L_SEQ * DI) / 256, 256>>>(
            conv_w + (size_t)i * DI * DCONV, conv_b + (size_t)i * DI);

        // dbl = xc @ x_proj_w^T   (1024 x 80, K=1536)  — small, fp32
        {
            dim3 g2((DBL_W + GBN - 1) / GBN, L_SEQ / GBM);
            gemm_tn<0><<<g2, 256>>>(xc, DI,
                                    x_proj_w + (size_t)i * DBL_W * DI, DI,
                                    dbl, DBL_W, DBL_W, DI, 0);
        }

        // dt = softplus(dbl[:, :48] @ dt_proj_w^T + b)  (1024 x 1536, K=48)
        {
            dim3 g3((DI + GBN - 1) / GBN, L_SEQ / GBM);
            gemm_tn<1><<<g3, 256>>>(dbl, DBL_W,
                                    dt_proj_w + (size_t)i * DI * DTRANK, DTRANK,
                                    dt, DI, DI, DTRANK,
                                    dt_proj_b + (size_t)i * DI);
        }

        scan_kernel<<<DI / 8, 128>>>(A_log + (size_t)i * DI * DSTATE);

        y_epi_split_kernel<<<(L_SEQ * DI) / 256, 256>>>(D_param + (size_t)i * DI);

        split2_kernel<<<(DM * DI) / 256, 256>>>(out_proj_w + (size_t)i * DM * DI,
                                                outw_s, DM, DI,
                                                (long long)DM * DI);

        // part[z] = y @ out_proj_w^T, split-K=6 over 144 virtual chunks
        {
            dim3 g4(L_SEQ / TCM, DM / TCN, 6);
            mma_gemm<<<g4, 128>>>(y_s, outw_s, part, DM, DM, DI,
                                  3 * (DI / TCK) / 6, (long long)L_SEQ * DM);
        }
        combine_kernel<<<(L_SEQ * DM) / 256, 256>>>();   // h += sum of 6 partials
    }

    rmsnorm_split_kernel<<<L_SEQ, 256>>>(h, hn_s, norm_f_w);
    {
        long long tot = (long long)VOCAB_PAD * DM;
        split2_kernel<<<(unsigned)((tot + 255) / 256), 256>>>(emb, emb_s, VOCAB, DM, tot);
    }

    // logits = hn @ emb^T   (1024 x 50280, K=768) — dominant GEMM
    {
        dim3 g5(L_SEQ / TCM, VOCAB_PAD / TCN, 1);
        mma_gemm<<<g5, 128>>>(hn_s, emb_s, logits, VOCAB, VOCAB, DM,
                              3 * (DM / TCK), 0);
    }
}

// round 9
// speedup vs baseline: 3.4373x; 1.4603x over previous
#include <cuda_runtime.h>
#include <cuda_bf16.h>
#include <math.h>
#include <stdint.h>

#define L_SEQ 1024
#define DM 768
#define DI 1536
#define DSTATE 16
#define DCONV 4
#define DTRANK 48
#define NLAYER 4
#define VOCAB 50280
#define VOCAB_PAD 50304            // 393*128
#define DBL_W (DTRANK + 2*DSTATE)  // 80
#define NCHUNK 8
#define LCHUNK (L_SEQ / NCHUNK)    // 128
#define XPJ_SPLITK 9

// ---------------- scratch (device globals) ---------------------------------
__device__ float g_h [L_SEQ*DM];
__device__ float g_xz[L_SEQ*2*DI];
__device__ float g_xc[L_SEQ*DI];
__device__ float g_dbl[L_SEQ*DBL_W];
__device__ float g_dblp[XPJ_SPLITK * L_SEQ * DBL_W];  // x_proj split-K partials
__device__ float g_dt[L_SEQ*DI];
__device__ float g_y [L_SEQ*DI];
__device__ float g_part[6 * L_SEQ * DM];   // out_proj split-K partials

// chunked-scan state buffers
__device__ float g_sc_end [NCHUNK*DI*DSTATE];
__device__ float g_sc_prod[NCHUNK*DI*DSTATE];
__device__ float g_sc_start[NCHUNK*DI*DSTATE];

// bf16 2-segment split buffers: row = [hi | lo], width 2K.
__device__ __nv_bfloat16 g_emb_s [(size_t)VOCAB_PAD * 2 * DM];
__device__ __nv_bfloat16 g_hn_s  [(size_t)L_SEQ     * 2 * DM];
__device__ __nv_bfloat16 g_inw_s [(size_t)2*DI      * 2 * DM];
__device__ __nv_bfloat16 g_y_s   [(size_t)L_SEQ     * 2 * DI];   // xc split, then y split
__device__ __nv_bfloat16 g_outw_s[(size_t)DM        * 2 * DI];
__device__ __nv_bfloat16 g_xw_s  [(size_t)128       * 2 * DI];   // x_proj_w padded 80->128

__device__ __forceinline__ uint32_t s2u(const void* p){
    uint32_t a;
    asm("{ .reg .u64 t; cvta.to.shared.u64 t, %1; cvt.u32.u64 %0, t; }"
        : "=r"(a) : "l"(p));
    return a;
}

// ---------------- embedding gather ----------------------------------------
__global__ void embed_kernel(const int* __restrict__ ids,
                             const float* __restrict__ emb)
{
    int l = blockIdx.x;
    int id = ids[l];
    const float4* src = (const float4*)(emb + (size_t)id * DM);
    float4* dst = (float4*)(g_h + (size_t)l * DM);
    dst[threadIdx.x] = src[threadIdx.x];
}

// ---------------- rmsnorm + fused [h|l] split ------------------------------
__global__ void rmsnorm_split_kernel(const float* __restrict__ in,
                                     __nv_bfloat16* __restrict__ out_s,
                                     const float* __restrict__ w)
{
    int l = blockIdx.x;
    const float* x = in + (size_t)l * DM;
    float ss = 0.f;
    for (int i = threadIdx.x; i < DM; i += 256) {
        float v = x[i];
        ss = fmaf(v, v, ss);
    }
    #pragma unroll
    for (int off = 16; off >= 1; off >>= 1)
        ss += __shfl_xor_sync(0xffffffffu, ss, off);

    __shared__ float red[8];
    __shared__ float scale_s;
    int warp = threadIdx.x >> 5, lane = threadIdx.x & 31;
    if (lane == 0) red[warp] = ss;
    __syncthreads();
    if (threadIdx.x == 0) {
        float t = 0.f;
        #pragma unroll
        for (int i = 0; i < 8; i++) t += red[i];
        scale_s = rsqrtf(t / (float)DM + 1e-5f);
    }
    __syncthreads();
    float scale = scale_s;
    __nv_bfloat16* row = out_s + (size_t)l * 2 * DM;
    for (int i = threadIdx.x; i < DM; i += 256) {
        float v = x[i] * scale * w[i];
        __nv_bfloat16 h = __float2bfloat16(v);
        __nv_bfloat16 lo = __float2bfloat16(v - __bfloat162float(h));
        row[i]      = h;
        row[DM + i] = lo;
    }
}

// ---------------- generic [h|l] split (zero-pads rows R..Rpad) -------------
__global__ void split2_kernel(const float* __restrict__ src,
                              __nv_bfloat16* __restrict__ dst,
                              int R, int K, long long total)
{
    long long idx = (long long)blockIdx.x * blockDim.x + threadIdx.x;
    if (idx >= total) return;
    int r = (int)(idx / K);
    int k = (int)(idx - (long long)r * K);
    float v = (r < R) ? src[(size_t)r * K + k] : 0.f;
    __nv_bfloat16 h = __float2bfloat16(v);
    __nv_bfloat16 l = __float2bfloat16(v - __bfloat162float(h));
    __nv_bfloat16* row = dst + (size_t)r * 2 * K;
    row[k]     = h;
    row[K + k] = l;
}

// ---------------- depthwise causal conv + bias + silu + fused xc split -----
__global__ void conv_silu_kernel(const float* __restrict__ cw,
                                 const float* __restrict__ cb)
{
    int idx = blockIdx.x * blockDim.x + threadIdx.x;
    int l = idx / DI;
    int d = idx - l * DI;
    float4 wv = *(const float4*)(cw + (size_t)d * 4);
    float acc = cb[d];
    const float* wj = (const float*)&wv;
    #pragma unroll
    for (int j = 0; j < DCONV; j++) {
        int ll = l - (DCONV - 1) + j;
        if (ll >= 0) acc = fmaf(wj[j], g_xz[(size_t)ll * 2 * DI + d], acc);
    }
    acc = acc / (1.f + __expf(-acc));
    g_xc[idx] = acc;
    // split-bf16 copy for the x_proj tensor GEMM (buffer reused by y later)
    __nv_bfloat16 h = __float2bfloat16(acc);
    __nv_bfloat16 lo = __float2bfloat16(acc - __bfloat162float(h));
    __nv_bfloat16* row = g_y_s + (size_t)l * 2 * DI;
    row[d]      = h;
    row[DI + d] = lo;
}

// ---------------- chunked selective scan -----------------------------------
// pass1: per (channel, chunk): end state with s0=0, and decay product.
__global__ void scan_pass1_kernel(const float* __restrict__ A_log)
{
    int gw   = threadIdx.x >> 5;              // warp in block (4)
    int lane = threadIdx.x & 31;
    int n    = lane & 15;
    int ch   = (blockIdx.x * 4 + gw) * 2 + (lane >> 4);
    int c    = blockIdx.y;

    float Aval = -__expf(A_log[(size_t)ch * DSTATE + n]);
    float s = 0.f, prod = 1.f;
    int l0 = c * LCHUNK;
    for (int l = l0; l < l0 + LCHUNK; l++) {
        float dtv = g_dt [(size_t)l * DI + ch];
        float xcv = g_xc [(size_t)l * DI + ch];
        float Bv  = g_dbl[(size_t)l * DBL_W + DTRANK + n];
        float dA  = __expf(dtv * Aval);
        s = dA * s + dtv * Bv * xcv;
        prod *= dA;
    }
    int idx = (c * DI + ch) * DSTATE + n;
    g_sc_end[idx]  = s;
    g_sc_prod[idx] = prod;
}

// fix-up: chain chunk states sequentially (tiny).
__global__ void scan_fix_kernel()
{
    int i = blockIdx.x * blockDim.x + threadIdx.x;   // < DI*DSTATE
    float s = 0.f;
    #pragma unroll
    for (int c = 0; c < NCHUNK; c++) {
        g_sc_start[c * DI * DSTATE + i] = s;
        s = g_sc_prod[c * DI * DSTATE + i] * s + g_sc_end[c * DI * DSTATE + i];
    }
}

// pass2: replay each chunk from its true start state, compute y.
__global__ void scan_pass2_kernel(const float* __restrict__ A_log)
{
    int gw   = threadIdx.x >> 5;
    int lane = threadIdx.x & 31;
    int n    = lane & 15;
    int ch   = (blockIdx.x * 4 + gw) * 2 + (lane >> 4);
    int c    = blockIdx.y;

    float Aval = -__expf(A_log[(size_t)ch * DSTATE + n]);
    float s = g_sc_start[(c * DI + ch) * DSTATE + n];
    int l0 = c * LCHUNK;
    for (int l = l0; l < l0 + LCHUNK; l++) {
        float dtv = g_dt [(size_t)l * DI + ch];
        float xcv = g_xc [(size_t)l * DI + ch];
        float Bv  = g_dbl[(size_t)l * DBL_W + DTRANK + n];
        float Cv  = g_dbl[(size_t)l * DBL_W + DTRANK + DSTATE + n];
        s = __expf(dtv * Aval) * s + dtv * Bv * xcv;
        float p = s * Cv;
        p += __shfl_xor_sync(0xffffffffu, p, 1);
        p += __shfl_xor_sync(0xffffffffu, p, 2);
        p += __shfl_xor_sync(0xffffffffu, p, 4);
        p += __shfl_xor_sync(0xffffffffu, p, 8);
        if (n == 0) g_y[(size_t)l * DI + ch] = p;
    }
}

// ---------------- y = (y + xc*D) * silu(z), fused [h|l] split --------------
__global__ void y_epi_split_kernel(const float* __restrict__ Dp)
{
    int idx = blockIdx.x * blockDim.x + threadIdx.x;   // < L_SEQ*DI
    int l = idx / DI;
    int d = idx - l * DI;
    float z  = g_xz[(size_t)l * 2 * DI + DI + d];
    float yv = g_y[idx] + g_xc[idx] * Dp[d];
    yv *= z / (1.f + __expf(-z));
    __nv_bfloat16 h = __float2bfloat16(yv);
    __nv_bfloat16 lo = __float2bfloat16(yv - __bfloat162float(h));
    __nv_bfloat16* row = g_y_s + (size_t)l * 2 * DI;
    row[d]      = h;
    row[DI + d] = lo;
}

// ---------------- split-K combines -----------------------------------------
__global__ void combine_h_kernel()      // h += sum of 6 out_proj partials
{
    int idx = blockIdx.x * blockDim.x + threadIdx.x;   // < L_SEQ*DM
    const int S = L_SEQ * DM;
    float a = g_part[idx]         + g_part[idx + S]     + g_part[idx + 2 * S];
    float b = g_part[idx + 3 * S] + g_part[idx + 4 * S] + g_part[idx + 5 * S];
    g_h[idx] += a + b;
}

__global__ void combine_dbl_kernel()    // dbl = sum of 9 x_proj partials
{
    int idx = blockIdx.x * blockDim.x + threadIdx.x;   // < L_SEQ*DBL_W
    const int S = L_SEQ * DBL_W;
    float a = 0.f;
    #pragma unroll
    for (int z = 0; z < XPJ_SPLITK; z++) a += g_dblp[z * S + idx];
    g_dbl[idx] = a;
}

// ---------------- fp32 TN GEMM (dt_proj only) ------------------------------
#define GBM 128
#define GBN 64
#define GBK 16

template<int EPI>
__global__ __launch_bounds__(256)
void gemm_tn(const float* __restrict__ A, int lda,
             const float* __restrict__ B, int ldb,
             float* __restrict__ C, int ldc,
             int N, int K, const float* __restrict__ bias)
{
    __shared__ float As[GBK][GBM + 4];
    __shared__ float Bs[GBK][GBN + 4];

    const int bm  = blockIdx.y * GBM;
    const int bn  = blockIdx.x * GBN;
    const int tid = threadIdx.x;
    const int tx  = tid & 15;
    const int ty  = tid >> 4;
    const int a_row = tid >> 1;
    const int a_k   = (tid & 1) * 8;
    const int b_row = tid >> 2;
    const int b_k   = (tid & 3) * 4;

    float acc[8][4];
    #pragma unroll
    for (int i = 0; i < 8; i++)
        #pragma unroll
        for (int j = 0; j < 4; j++) acc[i][j] = 0.f;

    const float* Aptr = A + (size_t)(bm + a_row) * lda + a_k;
    const int gbn = bn + b_row;
    const float* Bptr = (gbn < N) ? (B + (size_t)gbn * ldb + b_k) : 0;

    for (int k0 = 0; k0 < K; k0 += GBK) {
        float4 av0 = *(const float4*)(Aptr + k0);
        float4 av1 = *(const float4*)(Aptr + k0 + 4);
        float4 bv  = Bptr ? *(const float4*)(Bptr + k0)
                          : make_float4(0.f, 0.f, 0.f, 0.f);

        As[a_k + 0][a_row] = av0.x; As[a_k + 1][a_row] = av0.y;
        As[a_k + 2][a_row] = av0.z; As[a_k + 3][a_row] = av0.w;
        As[a_k + 4][a_row] = av1.x; As[a_k + 5][a_row] = av1.y;
        As[a_k + 6][a_row] = av1.z; As[a_k + 7][a_row] = av1.w;
        Bs[b_k + 0][b_row] = bv.x;  Bs[b_k + 1][b_row] = bv.y;
        Bs[b_k + 2][b_row] = bv.z;  Bs[b_k + 3][b_row] = bv.w;
        __syncthreads();

        #pragma unroll
        for (int kk = 0; kk < GBK; kk++) {
            float ar[8], br[4];
            #pragma unroll
            for (int i = 0; i < 8; i++) ar[i] = As[kk][ty * 8 + i];
            #pragma unroll
            for (int j = 0; j < 4; j++) br[j] = Bs[kk][tx * 4 + j];
            #pragma unroll
            for (int i = 0; i < 8; i++)
                #pragma unroll
                for (int j = 0; j < 4; j++)
                    acc[i][j] = fmaf(ar[i], br[j], acc[i][j]);
        }
        __syncthreads();
    }

    #pragma unroll
    for (int i = 0; i < 8; i++) {
        int m = bm + ty * 8 + i;
        #pragma unroll
        for (int j = 0; j < 4; j++) {
            int n = bn + tx * 4 + j;
            if (n < N) {
                float v = acc[i][j];
                if (EPI == 1) {
                    v += bias[n];
                    v = fmaxf(v, 0.f) + log1pf(__expf(-fabsf(v)));
                }
                C[(size_t)m * ldc + n] = v;
            }
        }
    }
}

// ---------------- bf16 HMMA GEMM, 128x64 tile, 4 warps, 3-stage ------------
#define TCM 128
#define TCN 64
#define TCK 32
#define TC_ASZ (TCM*64)
#define TC_BSZ (TCN*64)
#define TC_STAGE (TC_ASZ + TC_BSZ)   // 12288

__device__ __forceinline__ void cp_async16(uint32_t s, const void* g)
{
    asm volatile("cp.async.cg.shared.global [%0], [%1], 16;\n"
                 :: "r"(s), "l"(g));
}
__device__ __forceinline__ void cp_commit(){ asm volatile("cp.async.commit_group;\n" ::: "memory"); }
template<int N> __device__ __forceinline__ void cp_wait(){ asm volatile("cp.async.wait_group %0;\n" :: "n"(N) : "memory"); }

__device__ __forceinline__ void ldsm_x4(uint32_t* r, uint32_t addr)
{
    asm volatile("ldmatrix.sync.aligned.m8n8.x4.shared.b16 {%0,%1,%2,%3}, [%4];"
                 : "=r"(r[0]), "=r"(r[1]), "=r"(r[2]), "=r"(r[3]) : "r"(addr));
}
__device__ __forceinline__ void mma16816(float* c, const uint32_t* a, const uint32_t* b)
{
    asm volatile(
        "mma.sync.aligned.m16n8k16.row.col.f32.bf16.bf16.f32 "
        "{%0,%1,%2,%3}, {%4,%5,%6,%7}, {%8,%9}, {%0,%1,%2,%3};"
        : "+f"(c[0]), "+f"(c[1]), "+f"(c[2]), "+f"(c[3])
        : "r"(a[0]), "r"(a[1]), "r"(a[2]), "r"(a[3]), "r"(b[0]), "r"(b[1]));
}

__device__ __forceinline__ uint32_t swz(int row, int chunk){
    return (uint32_t)(row * 64 + ((chunk ^ ((row >> 1) & 3)) * 16));
}

__global__ __launch_bounds__(128, 4)
void mma_gemm(const __nv_bfloat16* __restrict__ A,
              const __nv_bfloat16* __restrict__ B,
              float* __restrict__ C, int ldc, int N, int Kreal,
              int cps, long long partStride)
{
    __shared__ __align__(16) char sm[3 * TC_STAGE];   // 36 KB
    const uint32_t sbase = s2u(sm);
    const int tid  = threadIdx.x;
    const int wid  = tid >> 5, lane = tid & 31;
    const int wm   = wid & 1;
    const int wn   = wid >> 1;
    const int bm   = blockIdx.x * TCM;
    const int bn   = blockIdx.y * TCN;
    const int KC   = Kreal / TCK;
    const int c0   = blockIdx.z * cps;
    const int c1   = c0 + cps;
    C += (long long)blockIdx.z * partStride;

    const int lda = 2 * Kreal;

    const int ar0 = (tid + 0*128) >> 2,  ak0 = (tid + 0*128) & 3;
    const int ar1 = (tid + 1*128) >> 2,  ak1 = (tid + 1*128) & 3;
    const int ar2 = (tid + 2*128) >> 2,  ak2 = (tid + 2*128) & 3;
    const int ar3 = (tid + 3*128) >> 2,  ak3 = (tid + 3*128) & 3;
    const __nv_bfloat16* Ag0 = A + (size_t)(bm + ar0) * lda + ak0 * 8;
    const __nv_bfloat16* Ag1 = A + (size_t)(bm + ar1) * lda + ak1 * 8;
    const __nv_bfloat16* Ag2 = A + (size_t)(bm + ar2) * lda + ak2 * 8;
    const __nv_bfloat16* Ag3 = A + (size_t)(bm + ar3) * lda + ak3 * 8;
    const __nv_bfloat16* Bg0 = B + (size_t)(bn + ar0) * lda + ak0 * 8;
    const __nv_bfloat16* Bg1 = B + (size_t)(bn + ar1) * lda + ak1 * 8;
    const uint32_t sa0 = sbase + swz(ar0, ak0);
    const uint32_t sa1 = sbase + swz(ar1, ak1);
    const uint32_t sa2 = sbase + swz(ar2, ak2);
    const uint32_t sa3 = sbase + swz(ar3, ak3);
    const uint32_t sb0 = sbase + TC_ASZ + swz(ar0, ak0);
    const uint32_t sb1 = sbase + TC_ASZ + swz(ar1, ak1);

    float acc[4][4][4];
    #pragma unroll
    for (int i = 0; i < 4; i++)
        #pragma unroll
        for (int j = 0; j < 4; j++)
            #pragma unroll
            for (int t = 0; t < 4; t++) acc[i][j][t] = 0.f;

    const int a_row = wm * 64 + (lane & 15);
    const int a_k8s = lane >> 4;
    const int b_row = wn * 32 + (lane & 7) + ((lane >> 4) << 3);
    const int b_k8s = (lane >> 3) & 1;

    #define LOAD_STAGE(cc, so) do { \
        int ac = ((cc) < 2*KC ? (cc) : (cc) - 2*KC) * TCK; \
        int bc = ((cc) < KC   ? (cc) : (cc) - KC)   * TCK; \
        cp_async16(sa0 + (so), Ag0 + ac); cp_async16(sa1 + (so), Ag1 + ac); \
        cp_async16(sa2 + (so), Ag2 + ac); cp_async16(sa3 + (so), Ag3 + ac); \
        cp_async16(sb0 + (so), Bg0 + bc); cp_async16(sb1 + (so), Bg1 + bc); \
        cp_commit(); \
    } while (0)

    LOAD_STAGE(c0, 0);
    if (c1 - c0 > 1) LOAD_STAGE(c0 + 1, TC_STAGE);

    for (int c = c0; c < c1; c++) {
        if (c < c1 - 1) cp_wait<1>(); else cp_wait<0>();
        __syncthreads();

        if (c + 2 < c1) {
            const uint32_t so = (uint32_t)(((c + 2 - c0) % 3) * TC_STAGE);
            LOAD_STAGE(c + 2, so);
        }

        const uint32_t sA = sbase + ((c - c0) % 3) * TC_STAGE;
        const uint32_t sB = sA + TC_ASZ;

        #pragma unroll
        for (int k16 = 0; k16 < 2; k16++) {
            uint32_t afrag[4][4];
            #pragma unroll
            for (int mt = 0; mt < 4; mt++) {
                int row = a_row + mt * 16;
                ldsm_x4(afrag[mt], sA + swz(row, k16 * 2 + a_k8s));
            }
            uint32_t bfrag[4][2];
            #pragma unroll
            for (int np = 0; np < 2; np++) {
                int row = b_row + np * 16;
                uint32_t t[4];
                ldsm_x4(t, sB + swz(row, k16 * 2 + b_k8s));
                bfrag[np * 2 + 0][0] = t[0]; bfrag[np * 2 + 0][1] = t[1];
                bfrag[np * 2 + 1][0] = t[2]; bfrag[np * 2 + 1][1] = t[3];
            }
            #pragma unroll
            for (int mt = 0; mt < 4; mt++)
                #pragma unroll
                for (int nt = 0; nt < 4; nt++)
                    mma16816(acc[mt][nt], afrag[mt], bfrag[nt]);
        }
    }
    #undef LOAD_STAGE

    const int erow = lane >> 2;
    const int ecol = (lane & 3) * 2;
    #pragma unroll
    for (int mt = 0; mt < 4; mt++) {
        #pragma unroll
        for (int nt = 0; nt < 4; nt++) {
            int m0 = bm + wm * 64 + mt * 16 + erow;
            int n0 = bn + wn * 32 + nt * 8 + ecol;
            if (n0 < N) {
                float* p0 = C + (size_t)m0 * ldc + n0;
                float* p1 = p0 + 8 * ldc;
                *(float2*)p0 = make_float2(acc[mt][nt][0], acc[mt][nt][1]);
                *(float2*)p1 = make_float2(acc[mt][nt][2], acc[mt][nt][3]);
            }
        }
    }
}

// ---------------- orchestration --------------------------------------------
extern "C" void kernel_launch(void* const* d_in, const int* in_sizes, int n_in,
                              void* d_out, int out_size)
{
    const int*   ids        = (const int*)  d_in[0];
    const float* emb        = (const float*)d_in[1];
    const float* in_proj_w  = (const float*)d_in[2];
    const float* conv_w     = (const float*)d_in[3];
    const float* conv_b     = (const float*)d_in[4];
    const float* x_proj_w   = (const float*)d_in[5];
    const float* dt_proj_w  = (const float*)d_in[6];
    const float* dt_proj_b  = (const float*)d_in[7];
    const float* A_log      = (const float*)d_in[8];
    const float* D_param    = (const float*)d_in[9];
    const float* out_proj_w = (const float*)d_in[10];
    const float* norm_w     = (const float*)d_in[11];
    const float* norm_f_w   = (const float*)d_in[12];
    float* logits = (float*)d_out;

    float *h, *xz, *xc, *dbl, *dblp, *dt, *y, *part;
    cudaGetSymbolAddress((void**)&h,    g_h);
    cudaGetSymbolAddress((void**)&xz,   g_xz);
    cudaGetSymbolAddress((void**)&xc,   g_xc);
    cudaGetSymbolAddress((void**)&dbl,  g_dbl);
    cudaGetSymbolAddress((void**)&dblp, g_dblp);
    cudaGetSymbolAddress((void**)&dt,   g_dt);
    cudaGetSymbolAddress((void**)&y,    g_y);
    cudaGetSymbolAddress((void**)&part, g_part);

    __nv_bfloat16 *emb_s, *hn_s, *inw_s, *y_s, *outw_s, *xw_s;
    cudaGetSymbolAddress((void**)&emb_s,  g_emb_s);
    cudaGetSymbolAddress((void**)&hn_s,   g_hn_s);
    cudaGetSymbolAddress((void**)&inw_s,  g_inw_s);
    cudaGetSymbolAddress((void**)&y_s,    g_y_s);
    cudaGetSymbolAddress((void**)&outw_s, g_outw_s);
    cudaGetSymbolAddress((void**)&xw_s,   g_xw_s);

    embed_kernel<<<L_SEQ, DM / 4>>>(ids, emb);

    for (int i = 0; i < NLAYER; i++) {
        rmsnorm_split_kernel<<<L_SEQ, 256>>>(h, hn_s, norm_w + (size_t)i * DM);
        split2_kernel<<<(2 * DI * DM) / 256, 256>>>(in_proj_w + (size_t)i * 2 * DI * DM,
                                                    inw_s, 2 * DI, DM,
                                                    (long long)2 * DI * DM);

        // xz = hn @ in_proj_w^T   (1024 x 3072, K=768)
        {
            dim3 g1(L_SEQ / TCM, 2 * DI / TCN, 1);
            mma_gemm<<<g1, 128>>>(hn_s, inw_s, xz, 2 * DI, 2 * DI, DM,
                                  3 * (DM / TCK), 0);
        }

        conv_silu_kernel<<<(L_SEQ * DI) / 256, 256>>>(
            conv_w + (size_t)i * DI * DCONV, conv_b + (size_t)i * DI);

        // x_proj weights: 80 rows -> padded to 128, split bf16
        split2_kernel<<<(128 * DI) / 256, 256>>>(x_proj_w + (size_t)i * DBL_W * DI,
                                                 xw_s, DBL_W, DI,
                                                 (long long)128 * DI);

        // dbl = xc @ x_proj_w^T   (1024 x 80, K=1536), tensor path, split-K=9
        {
            dim3 g2(L_SEQ / TCM, 128 / TCN, XPJ_SPLITK);
            mma_gemm<<<g2, 128>>>(y_s /*xc split*/, xw_s, dblp, DBL_W, DBL_W, DI,
                                  3 * (DI / TCK) / XPJ_SPLITK,
                                  (long long)L_SEQ * DBL_W);
        }
        combine_dbl_kernel<<<(L_SEQ * DBL_W) / 256, 256>>>();

        // dt = softplus(dbl[:, :48] @ dt_proj_w^T + b)  (1024 x 1536, K=48)
        {
            dim3 g3((DI + GBN - 1) / GBN, L_SEQ / GBM);
            gemm_tn<1><<<g3, 256>>>(dbl, DBL_W,
                                    dt_proj_w + (size_t)i * DI * DTRANK, DTRANK,
                                    dt, DI, DI, DTRANK,
                                    dt_proj_b + (size_t)i * DI);
        }

        // chunked selective scan
        {
            const float* Al = A_log + (size_t)i * DI * DSTATE;
            dim3 gs(DI / 8, NCHUNK);
            scan_pass1_kernel<<<gs, 128>>>(Al);
            scan_fix_kernel<<<(DI * DSTATE) / 256, 256>>>();
            scan_pass2_kernel<<<gs, 128>>>(Al);
        }

        y_epi_split_kernel<<<(L_SEQ * DI) / 256, 256>>>(D_param + (size_t)i * DI);

        split2_kernel<<<(DM * DI) / 256, 256>>>(out_proj_w + (size_t)i * DM * DI,
                                                outw_s, DM, DI,
                                                (long long)DM * DI);

        // part[z] = y @ out_proj_w^T, split-K=6
        {
            dim3 g4(L_SEQ / TCM, DM / TCN, 6);
            mma_gemm<<<g4, 128>>>(y_s, outw_s, part, DM, DM, DI,
                                  3 * (DI / TCK) / 6, (long long)L_SEQ * DM);
        }
        combine_h_kernel<<<(L_SEQ * DM) / 256, 256>>>();
    }

    rmsnorm_split_kernel<<<L_SEQ, 256>>>(h, hn_s, norm_f_w);
    {
        long long tot = (long long)VOCAB_PAD * DM;
        split2_kernel<<<(unsigned)((tot + 255) / 256), 256>>>(emb, emb_s, VOCAB, DM, tot);
    }

    // logits = hn @ emb^T   (1024 x 50280, K=768) — dominant GEMM
    {
        dim3 g5(L_SEQ / TCM, VOCAB_PAD / TCN, 1);
        mma_gemm<<<g5, 128>>>(hn_s, emb_s, logits, VOCAB, VOCAB, DM,
                              3 * (DM / TCK), 0);
    }
}

// round 10
// speedup vs baseline: 4.8602x; 1.4139x over previous
#include <cuda_runtime.h>
#include <cuda_bf16.h>
#include <math.h>
#include <stdint.h>

#define L_SEQ 1024
#define DM 768
#define DI 1536
#define DSTATE 16
#define DCONV 4
#define DTRANK 48
#define NLAYER 4
#define VOCAB 50280
#define VOCAB_PAD 50304            // 393*128
#define DBL_W (DTRANK + 2*DSTATE)  // 80
#define NCHUNK 16
#define LCHUNK (L_SEQ / NCHUNK)    // 64
#define XPJ_SPLITK 9

// ---------------- scratch (device globals) ---------------------------------
__device__ float g_h [L_SEQ*DM];
__device__ float g_xz[L_SEQ*2*DI];
__device__ float g_xc[L_SEQ*DI];
__device__ float g_dbl[L_SEQ*DBL_W];
__device__ float g_dblp[XPJ_SPLITK * L_SEQ * DBL_W];  // x_proj split-K partials
__device__ float g_dt[L_SEQ*DI];
__device__ float g_y [L_SEQ*DI];
__device__ float g_part[6 * L_SEQ * DM];   // out_proj split-K partials

// chunked-scan state buffers
__device__ float g_sc_end [NCHUNK*DI*DSTATE];
__device__ float g_sc_prod[NCHUNK*DI*DSTATE];
__device__ float g_sc_start[NCHUNK*DI*DSTATE];

// bf16 2-segment split buffers: row = [hi | lo], width 2K.
__device__ __nv_bfloat16 g_emb_s [(size_t)VOCAB_PAD * 2 * DM];
__device__ __nv_bfloat16 g_hn_s  [(size_t)L_SEQ     * 2 * DM];
__device__ __nv_bfloat16 g_inw_s [(size_t)2*DI      * 2 * DM];
__device__ __nv_bfloat16 g_y_s   [(size_t)L_SEQ     * 2 * DI];   // xc split, then y split
__device__ __nv_bfloat16 g_outw_s[(size_t)DM        * 2 * DI];
__device__ __nv_bfloat16 g_xw_s  [(size_t)128       * 2 * DI];   // x_proj_w padded 80->128

__device__ __forceinline__ uint32_t s2u(const void* p){
    uint32_t a;
    asm("{ .reg .u64 t; cvta.to.shared.u64 t, %1; cvt.u32.u64 %0, t; }"
        : "=r"(a) : "l"(p));
    return a;
}

// ---------------- embedding gather ----------------------------------------
__global__ void embed_kernel(const int* __restrict__ ids,
                             const float* __restrict__ emb)
{
    int l = blockIdx.x;
    int id = ids[l];
    const float4* src = (const float4*)(emb + (size_t)id * DM);
    float4* dst = (float4*)(g_h + (size_t)l * DM);
    dst[threadIdx.x] = src[threadIdx.x];
}

// ---------------- rmsnorm + fused [h|l] split ------------------------------
__global__ void rmsnorm_split_kernel(const float* __restrict__ in,
                                     __nv_bfloat16* __restrict__ out_s,
                                     const float* __restrict__ w)
{
    int l = blockIdx.x;
    const float* x = in + (size_t)l * DM;
    float ss = 0.f;
    for (int i = threadIdx.x; i < DM; i += 256) {
        float v = x[i];
        ss = fmaf(v, v, ss);
    }
    #pragma unroll
    for (int off = 16; off >= 1; off >>= 1)
        ss += __shfl_xor_sync(0xffffffffu, ss, off);

    __shared__ float red[8];
    __shared__ float scale_s;
    int warp = threadIdx.x >> 5, lane = threadIdx.x & 31;
    if (lane == 0) red[warp] = ss;
    __syncthreads();
    if (threadIdx.x == 0) {
        float t = 0.f;
        #pragma unroll
        for (int i = 0; i < 8; i++) t += red[i];
        scale_s = rsqrtf(t / (float)DM + 1e-5f);
    }
    __syncthreads();
    float scale = scale_s;
    __nv_bfloat16* row = out_s + (size_t)l * 2 * DM;
    for (int i = threadIdx.x; i < DM; i += 256) {
        float v = x[i] * scale * w[i];
        __nv_bfloat16 h = __float2bfloat16(v);
        __nv_bfloat16 lo = __float2bfloat16(v - __bfloat162float(h));
        row[i]      = h;
        row[DM + i] = lo;
    }
}

// ---------------- generic [h|l] split (zero-pads rows R..Rpad) -------------
__global__ void split2_kernel(const float* __restrict__ src,
                              __nv_bfloat16* __restrict__ dst,
                              int R, int K, long long total)
{
    long long idx = (long long)blockIdx.x * blockDim.x + threadIdx.x;
    if (idx >= total) return;
    int r = (int)(idx / K);
    int k = (int)(idx - (long long)r * K);
    float v = (r < R) ? src[(size_t)r * K + k] : 0.f;
    __nv_bfloat16 h = __float2bfloat16(v);
    __nv_bfloat16 l = __float2bfloat16(v - __bfloat162float(h));
    __nv_bfloat16* row = dst + (size_t)r * 2 * K;
    row[k]     = h;
    row[K + k] = l;
}

// ---------------- depthwise causal conv + bias + silu + fused xc split -----
__global__ void conv_silu_kernel(const float* __restrict__ cw,
                                 const float* __restrict__ cb)
{
    int idx = blockIdx.x * blockDim.x + threadIdx.x;
    int l = idx / DI;
    int d = idx - l * DI;
    float4 wv = *(const float4*)(cw + (size_t)d * 4);
    float acc = cb[d];
    const float* wj = (const float*)&wv;
    #pragma unroll
    for (int j = 0; j < DCONV; j++) {
        int ll = l - (DCONV - 1) + j;
        if (ll >= 0) acc = fmaf(wj[j], g_xz[(size_t)ll * 2 * DI + d], acc);
    }
    acc = acc / (1.f + __expf(-acc));
    g_xc[idx] = acc;
    __nv_bfloat16 h = __float2bfloat16(acc);
    __nv_bfloat16 lo = __float2bfloat16(acc - __bfloat162float(h));
    __nv_bfloat16* row = g_y_s + (size_t)l * 2 * DI;
    row[d]      = h;
    row[DI + d] = lo;
}

// ---------------- chunked selective scan -----------------------------------
__global__ void scan_pass1_kernel(const float* __restrict__ A_log)
{
    int gw   = threadIdx.x >> 5;
    int lane = threadIdx.x & 31;
    int n    = lane & 15;
    int ch   = (blockIdx.x * 4 + gw) * 2 + (lane >> 4);
    int c    = blockIdx.y;

    float Aval = -__expf(A_log[(size_t)ch * DSTATE + n]);
    float s = 0.f, prod = 1.f;
    int l0 = c * LCHUNK;
    for (int l = l0; l < l0 + LCHUNK; l++) {
        float dtv = g_dt [(size_t)l * DI + ch];
        float xcv = g_xc [(size_t)l * DI + ch];
        float Bv  = g_dbl[(size_t)l * DBL_W + DTRANK + n];
        float dA  = __expf(dtv * Aval);
        s = dA * s + dtv * Bv * xcv;
        prod *= dA;
    }
    int idx = (c * DI + ch) * DSTATE + n;
    g_sc_end[idx]  = s;
    g_sc_prod[idx] = prod;
}

__global__ void scan_fix_kernel()
{
    int i = blockIdx.x * blockDim.x + threadIdx.x;   // < DI*DSTATE
    float s = 0.f;
    #pragma unroll
    for (int c = 0; c < NCHUNK; c++) {
        g_sc_start[c * DI * DSTATE + i] = s;
        s = g_sc_prod[c * DI * DSTATE + i] * s + g_sc_end[c * DI * DSTATE + i];
    }
}

__global__ void scan_pass2_kernel(const float* __restrict__ A_log)
{
    int gw   = threadIdx.x >> 5;
    int lane = threadIdx.x & 31;
    int n    = lane & 15;
    int ch   = (blockIdx.x * 4 + gw) * 2 + (lane >> 4);
    int c    = blockIdx.y;

    float Aval = -__expf(A_log[(size_t)ch * DSTATE + n]);
    float s = g_sc_start[(c * DI + ch) * DSTATE + n];
    int l0 = c * LCHUNK;
    for (int l = l0; l < l0 + LCHUNK; l++) {
        float dtv = g_dt [(size_t)l * DI + ch];
        float xcv = g_xc [(size_t)l * DI + ch];
        float Bv  = g_dbl[(size_t)l * DBL_W + DTRANK + n];
        float Cv  = g_dbl[(size_t)l * DBL_W + DTRANK + DSTATE + n];
        s = __expf(dtv * Aval) * s + dtv * Bv * xcv;
        float p = s * Cv;
        p += __shfl_xor_sync(0xffffffffu, p, 1);
        p += __shfl_xor_sync(0xffffffffu, p, 2);
        p += __shfl_xor_sync(0xffffffffu, p, 4);
        p += __shfl_xor_sync(0xffffffffu, p, 8);
        if (n == 0) g_y[(size_t)l * DI + ch] = p;
    }
}

// ---------------- y = (y + xc*D) * silu(z), fused [h|l] split --------------
__global__ void y_epi_split_kernel(const float* __restrict__ Dp)
{
    int idx = blockIdx.x * blockDim.x + threadIdx.x;   // < L_SEQ*DI
    int l = idx / DI;
    int d = idx - l * DI;
    float z  = g_xz[(size_t)l * 2 * DI + DI + d];
    float yv = g_y[idx] + g_xc[idx] * Dp[d];
    yv *= z / (1.f + __expf(-z));
    __nv_bfloat16 h = __float2bfloat16(yv);
    __nv_bfloat16 lo = __float2bfloat16(yv - __bfloat162float(h));
    __nv_bfloat16* row = g_y_s + (size_t)l * 2 * DI;
    row[d]      = h;
    row[DI + d] = lo;
}

// ---------------- split-K combines -----------------------------------------
__global__ void combine_h_kernel()
{
    int idx = blockIdx.x * blockDim.x + threadIdx.x;   // < L_SEQ*DM
    const int S = L_SEQ * DM;
    float a = g_part[idx]         + g_part[idx + S]     + g_part[idx + 2 * S];
    float b = g_part[idx + 3 * S] + g_part[idx + 4 * S] + g_part[idx + 5 * S];
    g_h[idx] += a + b;
}

__global__ void combine_dbl_kernel()
{
    int idx = blockIdx.x * blockDim.x + threadIdx.x;   // < L_SEQ*DBL_W
    const int S = L_SEQ * DBL_W;
    float a = 0.f;
    #pragma unroll
    for (int z = 0; z < XPJ_SPLITK; z++) a += g_dblp[z * S + idx];
    g_dbl[idx] = a;
}

// ---------------- fp32 TN GEMM (dt_proj only) ------------------------------
#define GBM 128
#define GBN 64
#define GBK 16

template<int EPI>
__global__ __launch_bounds__(256)
void gemm_tn(const float* __restrict__ A, int lda,
             const float* __restrict__ B, int ldb,
             float* __restrict__ C, int ldc,
             int N, int K, const float* __restrict__ bias)
{
    __shared__ float As[GBK][GBM + 4];
    __shared__ float Bs[GBK][GBN + 4];

    const int bm  = blockIdx.y * GBM;
    const int bn  = blockIdx.x * GBN;
    const int tid = threadIdx.x;
    const int tx  = tid & 15;
    const int ty  = tid >> 4;
    const int a_row = tid >> 1;
    const int a_k   = (tid & 1) * 8;
    const int b_row = tid >> 2;
    const int b_k   = (tid & 3) * 4;

    float acc[8][4];
    #pragma unroll
    for (int i = 0; i < 8; i++)
        #pragma unroll
        for (int j = 0; j < 4; j++) acc[i][j] = 0.f;

    const float* Aptr = A + (size_t)(bm + a_row) * lda + a_k;
    const int gbn = bn + b_row;
    const float* Bptr = (gbn < N) ? (B + (size_t)gbn * ldb + b_k) : 0;

    for (int k0 = 0; k0 < K; k0 += GBK) {
        float4 av0 = *(const float4*)(Aptr + k0);
        float4 av1 = *(const float4*)(Aptr + k0 + 4);
        float4 bv  = Bptr ? *(const float4*)(Bptr + k0)
                          : make_float4(0.f, 0.f, 0.f, 0.f);

        As[a_k + 0][a_row] = av0.x; As[a_k + 1][a_row] = av0.y;
        As[a_k + 2][a_row] = av0.z; As[a_k + 3][a_row] = av0.w;
        As[a_k + 4][a_row] = av1.x; As[a_k + 5][a_row] = av1.y;
        As[a_k + 6][a_row] = av1.z; As[a_k + 7][a_row] = av1.w;
        Bs[b_k + 0][b_row] = bv.x;  Bs[b_k + 1][b_row] = bv.y;
        Bs[b_k + 2][b_row] = bv.z;  Bs[b_k + 3][b_row] = bv.w;
        __syncthreads();

        #pragma unroll
        for (int kk = 0; kk < GBK; kk++) {
            float ar[8], br[4];
            #pragma unroll
            for (int i = 0; i < 8; i++) ar[i] = As[kk][ty * 8 + i];
            #pragma unroll
            for (int j = 0; j < 4; j++) br[j] = Bs[kk][tx * 4 + j];
            #pragma unroll
            for (int i = 0; i < 8; i++)
                #pragma unroll
                for (int j = 0; j < 4; j++)
                    acc[i][j] = fmaf(ar[i], br[j], acc[i][j]);
        }
        __syncthreads();
    }

    #pragma unroll
    for (int i = 0; i < 8; i++) {
        int m = bm + ty * 8 + i;
        #pragma unroll
        for (int j = 0; j < 4; j++) {
            int n = bn + tx * 4 + j;
            if (n < N) {
                float v = acc[i][j];
                if (EPI == 1) {
                    v += bias[n];
                    v = fmaxf(v, 0.f) + log1pf(__expf(-fabsf(v)));
                }
                C[(size_t)m * ldc + n] = v;
            }
        }
    }
}

// ---------------- bf16 HMMA GEMM, 128x64 tile, 4 warps, 4-stage pair loop --
// One barrier + one wait per TWO K-chunks. Requires even chunk count.
#define TCM 128
#define TCN 64
#define TCK 32
#define TC_ASZ (TCM*64)
#define TC_BSZ (TCN*64)
#define TC_STAGE (TC_ASZ + TC_BSZ)   // 12288; 4 stages = 48 KB

__device__ __forceinline__ void cp_async16(uint32_t s, const void* g)
{
    asm volatile("cp.async.cg.shared.global [%0], [%1], 16;\n"
                 :: "r"(s), "l"(g));
}
__device__ __forceinline__ void cp_commit(){ asm volatile("cp.async.commit_group;\n" ::: "memory"); }
template<int N> __device__ __forceinline__ void cp_wait(){ asm volatile("cp.async.wait_group %0;\n" :: "n"(N) : "memory"); }

__device__ __forceinline__ void ldsm_x4(uint32_t* r, uint32_t addr)
{
    asm volatile("ldmatrix.sync.aligned.m8n8.x4.shared.b16 {%0,%1,%2,%3}, [%4];"
                 : "=r"(r[0]), "=r"(r[1]), "=r"(r[2]), "=r"(r[3]) : "r"(addr));
}
__device__ __forceinline__ void mma16816(float* c, const uint32_t* a, const uint32_t* b)
{
    asm volatile(
        "mma.sync.aligned.m16n8k16.row.col.f32.bf16.bf16.f32 "
        "{%0,%1,%2,%3}, {%4,%5,%6,%7}, {%8,%9}, {%0,%1,%2,%3};"
        : "+f"(c[0]), "+f"(c[1]), "+f"(c[2]), "+f"(c[3])
        : "r"(a[0]), "r"(a[1]), "r"(a[2]), "r"(a[3]), "r"(b[0]), "r"(b[1]));
}

__device__ __forceinline__ uint32_t swz(int row, int chunk){
    return (uint32_t)(row * 64 + ((chunk ^ ((row >> 1) & 3)) * 16));
}

__global__ __launch_bounds__(128, 4)
void mma_gemm(const __nv_bfloat16* __restrict__ A,
              const __nv_bfloat16* __restrict__ B,
              float* __restrict__ C, int ldc, int N, int Kreal,
              int cps, long long partStride)
{
    __shared__ __align__(16) char sm[4 * TC_STAGE];   // 48 KB
    const uint32_t sbase = s2u(sm);
    const int tid  = threadIdx.x;
    const int wid  = tid >> 5, lane = tid & 31;
    const int wm   = wid & 1;
    const int wn   = wid >> 1;
    const int bm   = blockIdx.x * TCM;
    const int bn   = blockIdx.y * TCN;
    const int KC   = Kreal / TCK;
    const int c0   = blockIdx.z * cps;
    const int c1   = c0 + cps;          // cps even
    C += (long long)blockIdx.z * partStride;

    const int lda = 2 * Kreal;

    const int ar0 = (tid + 0*128) >> 2,  ak0 = (tid + 0*128) & 3;
    const int ar1 = (tid + 1*128) >> 2,  ak1 = (tid + 1*128) & 3;
    const int ar2 = (tid + 2*128) >> 2,  ak2 = (tid + 2*128) & 3;
    const int ar3 = (tid + 3*128) >> 2,  ak3 = (tid + 3*128) & 3;
    const __nv_bfloat16* Ag0 = A + (size_t)(bm + ar0) * lda + ak0 * 8;
    const __nv_bfloat16* Ag1 = A + (size_t)(bm + ar1) * lda + ak1 * 8;
    const __nv_bfloat16* Ag2 = A + (size_t)(bm + ar2) * lda + ak2 * 8;
    const __nv_bfloat16* Ag3 = A + (size_t)(bm + ar3) * lda + ak3 * 8;
    const __nv_bfloat16* Bg0 = B + (size_t)(bn + ar0) * lda + ak0 * 8;
    const __nv_bfloat16* Bg1 = B + (size_t)(bn + ar1) * lda + ak1 * 8;
    const uint32_t sa0 = sbase + swz(ar0, ak0);
    const uint32_t sa1 = sbase + swz(ar1, ak1);
    const uint32_t sa2 = sbase + swz(ar2, ak2);
    const uint32_t sa3 = sbase + swz(ar3, ak3);
    const uint32_t sb0 = sbase + TC_ASZ + swz(ar0, ak0);
    const uint32_t sb1 = sbase + TC_ASZ + swz(ar1, ak1);

    float acc[4][4][4];
    #pragma unroll
    for (int i = 0; i < 4; i++)
        #pragma unroll
        for (int j = 0; j < 4; j++)
            #pragma unroll
            for (int t = 0; t < 4; t++) acc[i][j][t] = 0.f;

    const int a_row = wm * 64 + (lane & 15);
    const int a_k8s = lane >> 4;
    const int b_row = wn * 32 + (lane & 7) + ((lane >> 4) << 3);
    const int b_k8s = (lane >> 3) & 1;

    #define LOAD_STAGE(cc) do { \
        uint32_t so = (uint32_t)(((cc) - c0) & 3) * TC_STAGE; \
        int ac = ((cc) < 2*KC ? (cc) : (cc) - 2*KC) * TCK; \
        int bc = ((cc) < KC   ? (cc) : (cc) - KC)   * TCK; \
        cp_async16(sa0 + so, Ag0 + ac); cp_async16(sa1 + so, Ag1 + ac); \
        cp_async16(sa2 + so, Ag2 + ac); cp_async16(sa3 + so, Ag3 + ac); \
        cp_async16(sb0 + so, Bg0 + bc); cp_async16(sb1 + so, Bg1 + bc); \
        cp_commit(); \
    } while (0)

    #define MATH_STAGE(cc) do { \
        const uint32_t sA = sbase + (uint32_t)(((cc) - c0) & 3) * TC_STAGE; \
        const uint32_t sB = sA + TC_ASZ; \
        _Pragma("unroll") \
        for (int k16 = 0; k16 < 2; k16++) { \
            uint32_t afrag[4][4]; \
            _Pragma("unroll") \
            for (int mt = 0; mt < 4; mt++) { \
                int row = a_row + mt * 16; \
                ldsm_x4(afrag[mt], sA + swz(row, k16 * 2 + a_k8s)); \
            } \
            uint32_t bfrag[4][2]; \
            _Pragma("unroll") \
            for (int np = 0; np < 2; np++) { \
                int row = b_row + np * 16; \
                uint32_t t[4]; \
                ldsm_x4(t, sB + swz(row, k16 * 2 + b_k8s)); \
                bfrag[np * 2 + 0][0] = t[0]; bfrag[np * 2 + 0][1] = t[1]; \
                bfrag[np * 2 + 1][0] = t[2]; bfrag[np * 2 + 1][1] = t[3]; \
            } \
            _Pragma("unroll") \
            for (int mt = 0; mt < 4; mt++) \
                _Pragma("unroll") \
                for (int nt = 0; nt < 4; nt++) \
                    mma16816(acc[mt][nt], afrag[mt], bfrag[nt]); \
        } \
    } while (0)

    // prologue: first pair
    LOAD_STAGE(c0);
    if (c1 - c0 > 1) LOAD_STAGE(c0 + 1);

    for (int c = c0; c < c1; c += 2) {
        cp_wait<0>();        // pair (c, c+1) resident
        __syncthreads();     // + all math on stages (c-2,c-1) complete
        if (c + 2 < c1) { LOAD_STAGE(c + 2); LOAD_STAGE(c + 3); }
        MATH_STAGE(c);
        MATH_STAGE(c + 1);
    }
    #undef LOAD_STAGE
    #undef MATH_STAGE

    const int erow = lane >> 2;
    const int ecol = (lane & 3) * 2;
    #pragma unroll
    for (int mt = 0; mt < 4; mt++) {
        #pragma unroll
        for (int nt = 0; nt < 4; nt++) {
            int m0 = bm + wm * 64 + mt * 16 + erow;
            int n0 = bn + wn * 32 + nt * 8 + ecol;
            if (n0 < N) {
                float* p0 = C + (size_t)m0 * ldc + n0;
                float* p1 = p0 + 8 * ldc;
                *(float2*)p0 = make_float2(acc[mt][nt][0], acc[mt][nt][1]);
                *(float2*)p1 = make_float2(acc[mt][nt][2], acc[mt][nt][3]);
            }
        }
    }
}

// ---------------- orchestration --------------------------------------------
extern "C" void kernel_launch(void* const* d_in, const int* in_sizes, int n_in,
                              void* d_out, int out_size)
{
    const int*   ids        = (const int*)  d_in[0];
    const float* emb        = (const float*)d_in[1];
    const float* in_proj_w  = (const float*)d_in[2];
    const float* conv_w     = (const float*)d_in[3];
    const float* conv_b     = (const float*)d_in[4];
    const float* x_proj_w   = (const float*)d_in[5];
    const float* dt_proj_w  = (const float*)d_in[6];
    const float* dt_proj_b  = (const float*)d_in[7];
    const float* A_log      = (const float*)d_in[8];
    const float* D_param    = (const float*)d_in[9];
    const float* out_proj_w = (const float*)d_in[10];
    const float* norm_w     = (const float*)d_in[11];
    const float* norm_f_w   = (const float*)d_in[12];
    float* logits = (float*)d_out;

    float *h, *xz, *xc, *dbl, *dblp, *dt, *y, *part;
    cudaGetSymbolAddress((void**)&h,    g_h);
    cudaGetSymbolAddress((void**)&xz,   g_xz);
    cudaGetSymbolAddress((void**)&xc,   g_xc);
    cudaGetSymbolAddress((void**)&dbl,  g_dbl);
    cudaGetSymbolAddress((void**)&dblp, g_dblp);
    cudaGetSymbolAddress((void**)&dt,   g_dt);
    cudaGetSymbolAddress((void**)&y,    g_y);
    cudaGetSymbolAddress((void**)&part, g_part);

    __nv_bfloat16 *emb_s, *hn_s, *inw_s, *y_s, *outw_s, *xw_s;
    cudaGetSymbolAddress((void**)&emb_s,  g_emb_s);
    cudaGetSymbolAddress((void**)&hn_s,   g_hn_s);
    cudaGetSymbolAddress((void**)&inw_s,  g_inw_s);
    cudaGetSymbolAddress((void**)&y_s,    g_y_s);
    cudaGetSymbolAddress((void**)&outw_s, g_outw_s);
    cudaGetSymbolAddress((void**)&xw_s,   g_xw_s);

    embed_kernel<<<L_SEQ, DM / 4>>>(ids, emb);

    for (int i = 0; i < NLAYER; i++) {
        rmsnorm_split_kernel<<<L_SEQ, 256>>>(h, hn_s, norm_w + (size_t)i * DM);
        split2_kernel<<<(2 * DI * DM) / 256, 256>>>(in_proj_w + (size_t)i * 2 * DI * DM,
                                                    inw_s, 2 * DI, DM,
                                                    (long long)2 * DI * DM);

        // xz = hn @ in_proj_w^T   (1024 x 3072, K=768)
        {
            dim3 g1(L_SEQ / TCM, 2 * DI / TCN, 1);
            mma_gemm<<<g1, 128>>>(hn_s, inw_s, xz, 2 * DI, 2 * DI, DM,
                                  3 * (DM / TCK), 0);
        }

        conv_silu_kernel<<<(L_SEQ * DI) / 256, 256>>>(
            conv_w + (size_t)i * DI * DCONV, conv_b + (size_t)i * DI);

        split2_kernel<<<(128 * DI) / 256, 256>>>(x_proj_w + (size_t)i * DBL_W * DI,
                                                 xw_s, DBL_W, DI,
                                                 (long long)128 * DI);

        // dbl = xc @ x_proj_w^T   (split-K=9, cps=16 even)
        {
            dim3 g2(L_SEQ / TCM, 128 / TCN, XPJ_SPLITK);
            mma_gemm<<<g2, 128>>>(y_s /*xc split*/, xw_s, dblp, DBL_W, DBL_W, DI,
                                  3 * (DI / TCK) / XPJ_SPLITK,
                                  (long long)L_SEQ * DBL_W);
        }
        combine_dbl_kernel<<<(L_SEQ * DBL_W) / 256, 256>>>();

        // dt = softplus(dbl[:, :48] @ dt_proj_w^T + b)
        {
            dim3 g3((DI + GBN - 1) / GBN, L_SEQ / GBM);
            gemm_tn<1><<<g3, 256>>>(dbl, DBL_W,
                                    dt_proj_w + (size_t)i * DI * DTRANK, DTRANK,
                                    dt, DI, DI, DTRANK,
                                    dt_proj_b + (size_t)i * DI);
        }

        // chunked selective scan (16 chunks of 64)
        {
            const float* Al = A_log + (size_t)i * DI * DSTATE;
            dim3 gs(DI / 8, NCHUNK);
            scan_pass1_kernel<<<gs, 128>>>(Al);
            scan_fix_kernel<<<(DI * DSTATE) / 256, 256>>>();
            scan_pass2_kernel<<<gs, 128>>>(Al);
        }

        y_epi_split_kernel<<<(L_SEQ * DI) / 256, 256>>>(D_param + (size_t)i * DI);

        split2_kernel<<<(DM * DI) / 256, 256>>>(out_proj_w + (size_t)i * DM * DI,
                                                outw_s, DM, DI,
                                                (long long)DM * DI);

        // part[z] = y @ out_proj_w^T, split-K=6 (cps=24 even)
        {
            dim3 g4(L_SEQ / TCM, DM / TCN, 6);
            mma_gemm<<<g4, 128>>>(y_s, outw_s, part, DM, DM, DI,
                                  3 * (DI / TCK) / 6, (long long)L_SEQ * DM);
        }
        combine_h_kernel<<<(L_SEQ * DM) / 256, 256>>>();
    }

    rmsnorm_split_kernel<<<L_SEQ, 256>>>(h, hn_s, norm_f_w);
    {
        long long tot = (long long)VOCAB_PAD * DM;
        split2_kernel<<<(unsigned)((tot + 255) / 256), 256>>>(emb, emb_s, VOCAB, DM, tot);
    }

    // logits = hn @ emb^T   (1024 x 50280, K=768) — dominant GEMM
    {
        dim3 g5(L_SEQ / TCM, VOCAB_PAD / TCN, 1);
        mma_gemm<<<g5, 128>>>(hn_s, emb_s, logits, VOCAB, VOCAB, DM,
                              3 * (DM / TCK), 0);
    }
}

// round 12
// speedup vs baseline: 5.1997x; 1.0699x over previous
#include <cuda_runtime.h>
#include <cuda_bf16.h>
#include <math.h>
#include <stdint.h>

#define L_SEQ 1024
#define DM 768
#define DI 1536
#define DSTATE 16
#define DCONV 4
#define DTRANK 48
#define NLAYER 4
#define VOCAB 50280
#define VOCAB_PAD 50304            // 393*128
#define DBL_W (DTRANK + 2*DSTATE)  // 80
#define NCHUNK 16
#define LCHUNK (L_SEQ / NCHUNK)    // 64
#define XPJ_SPLITK 9

// ---------------- scratch (device globals) ---------------------------------
__device__ float g_h [L_SEQ*DM];
__device__ float g_xz[L_SEQ*2*DI];
__device__ float g_xc[L_SEQ*DI];
__device__ float g_dbl[L_SEQ*DBL_W];
__device__ float g_dblp[XPJ_SPLITK * L_SEQ * DBL_W];
__device__ float g_dt[L_SEQ*DI];
__device__ float g_y [L_SEQ*DI];
__device__ float g_part[6 * L_SEQ * DM];

// chunked-scan state buffers
__device__ float g_sc_end [NCHUNK*DI*DSTATE];
__device__ float g_sc_prod[NCHUNK*DI*DSTATE];
__device__ float g_sc_start[NCHUNK*DI*DSTATE];

// bf16 2-segment split buffers: row = [hi | lo], width 2K.
__device__ __nv_bfloat16 g_emb_s [(size_t)VOCAB_PAD * 2 * DM];
__device__ __nv_bfloat16 g_hn_s  [(size_t)L_SEQ     * 2 * DM];
__device__ __nv_bfloat16 g_inw_s [(size_t)2*DI      * 2 * DM];
__device__ __nv_bfloat16 g_y_s   [(size_t)L_SEQ     * 2 * DI];
__device__ __nv_bfloat16 g_outw_s[(size_t)DM        * 2 * DI];
__device__ __nv_bfloat16 g_xw_s  [(size_t)128       * 2 * DI];

__device__ __forceinline__ uint32_t s2u(const void* p){
    uint32_t a;
    asm("{ .reg .u64 t; cvta.to.shared.u64 t, %1; cvt.u32.u64 %0, t; }"
        : "=r"(a) : "l"(p));
    return a;
}

// ---------------- embedding gather ----------------------------------------
__global__ void embed_kernel(const int* __restrict__ ids,
                             const float* __restrict__ emb)
{
    int l = blockIdx.x;
    int id = ids[l];
    const float4* src = (const float4*)(emb + (size_t)id * DM);
    float4* dst = (float4*)(g_h + (size_t)l * DM);
    dst[threadIdx.x] = src[threadIdx.x];
}

// ---------------- rmsnorm + fused [h|l] split ------------------------------
__global__ void rmsnorm_split_kernel(const float* __restrict__ in,
                                     __nv_bfloat16* __restrict__ out_s,
                                     const float* __restrict__ w)
{
    int l = blockIdx.x;
    const float* x = in + (size_t)l * DM;
    float ss = 0.f;
    for (int i = threadIdx.x; i < DM; i += 256) {
        float v = x[i];
        ss = fmaf(v, v, ss);
    }
    #pragma unroll
    for (int off = 16; off >= 1; off >>= 1)
        ss += __shfl_xor_sync(0xffffffffu, ss, off);

    __shared__ float red[8];
    __shared__ float scale_s;
    int warp = threadIdx.x >> 5, lane = threadIdx.x & 31;
    if (lane == 0) red[warp] = ss;
    __syncthreads();
    if (threadIdx.x == 0) {
        float t = 0.f;
        #pragma unroll
        for (int i = 0; i < 8; i++) t += red[i];
        scale_s = rsqrtf(t / (float)DM + 1e-5f);
    }
    __syncthreads();
    float scale = scale_s;
    __nv_bfloat16* row = out_s + (size_t)l * 2 * DM;
    for (int i = threadIdx.x; i < DM; i += 256) {
        float v = x[i] * scale * w[i];
        __nv_bfloat16 h = __float2bfloat16(v);
        __nv_bfloat16 lo = __float2bfloat16(v - __bfloat162float(h));
        row[i]      = h;
        row[DM + i] = lo;
    }
}

// ---------------- vectorized [h|l] split (4 elems/thread) ------------------
__device__ __forceinline__ uint32_t pack_bf(__nv_bfloat16 a, __nv_bfloat16 b){
    return (uint32_t)__bfloat16_as_ushort(a) |
           ((uint32_t)__bfloat16_as_ushort(b) << 16);
}

__global__ void split2_kernel(const float* __restrict__ src,
                              __nv_bfloat16* __restrict__ dst,
                              int R, int K, long long total4)
{
    long long idx = (long long)blockIdx.x * blockDim.x + threadIdx.x;
    if (idx >= total4) return;
    int kq = K >> 2;
    int r  = (int)(idx / kq);
    int k4 = (int)(idx - (long long)r * kq);
    float4 v = (r < R) ? ((const float4*)(src + (size_t)r * K))[k4]
                       : make_float4(0.f, 0.f, 0.f, 0.f);
    __nv_bfloat16 h0 = __float2bfloat16(v.x), h1 = __float2bfloat16(v.y);
    __nv_bfloat16 h2 = __float2bfloat16(v.z), h3 = __float2bfloat16(v.w);
    __nv_bfloat16 l0 = __float2bfloat16(v.x - __bfloat162float(h0));
    __nv_bfloat16 l1 = __float2bfloat16(v.y - __bfloat162float(h1));
    __nv_bfloat16 l2 = __float2bfloat16(v.z - __bfloat162float(h2));
    __nv_bfloat16 l3 = __float2bfloat16(v.w - __bfloat162float(h3));
    __nv_bfloat16* row = dst + (size_t)r * 2 * K;
    *(uint2*)(row + 4 * k4)     = make_uint2(pack_bf(h0, h1), pack_bf(h2, h3));
    *(uint2*)(row + K + 4 * k4) = make_uint2(pack_bf(l0, l1), pack_bf(l2, l3));
}

// ---------------- depthwise causal conv + bias + silu + fused xc split -----
__global__ void conv_silu_kernel(const float* __restrict__ cw,
                                 const float* __restrict__ cb)
{
    int idx = blockIdx.x * blockDim.x + threadIdx.x;
    int l = idx / DI;
    int d = idx - l * DI;
    float4 wv = *(const float4*)(cw + (size_t)d * 4);
    float acc = cb[d];
    const float* wj = (const float*)&wv;
    #pragma unroll
    for (int j = 0; j < DCONV; j++) {
        int ll = l - (DCONV - 1) + j;
        if (ll >= 0) acc = fmaf(wj[j], g_xz[(size_t)ll * 2 * DI + d], acc);
    }
    acc = acc / (1.f + __expf(-acc));
    g_xc[idx] = acc;
    __nv_bfloat16 h = __float2bfloat16(acc);
    __nv_bfloat16 lo = __float2bfloat16(acc - __bfloat162float(h));
    __nv_bfloat16* row = g_y_s + (size_t)l * 2 * DI;
    row[d]      = h;
    row[DI + d] = lo;
}

// ---------------- chunked selective scan -----------------------------------
__global__ void scan_pass1_kernel(const float* __restrict__ A_log)
{
    int gw   = threadIdx.x >> 5;
    int lane = threadIdx.x & 31;
    int n    = lane & 15;
    int ch   = (blockIdx.x * 4 + gw) * 2 + (lane >> 4);
    int c    = blockIdx.y;

    float Aval = -__expf(A_log[(size_t)ch * DSTATE + n]);
    float s = 0.f, prod = 1.f;
    int l0 = c * LCHUNK;
    for (int l = l0; l < l0 + LCHUNK; l++) {
        float dtv = g_dt [(size_t)l * DI + ch];
        float xcv = g_xc [(size_t)l * DI + ch];
        float Bv  = g_dbl[(size_t)l * DBL_W + DTRANK + n];
        float dA  = __expf(dtv * Aval);
        s = dA * s + dtv * Bv * xcv;
        prod *= dA;
    }
    int idx = (c * DI + ch) * DSTATE + n;
    g_sc_end[idx]  = s;
    g_sc_prod[idx] = prod;
}

__global__ void scan_fix_kernel()
{
    int i = blockIdx.x * blockDim.x + threadIdx.x;
    float s = 0.f;
    #pragma unroll
    for (int c = 0; c < NCHUNK; c++) {
        g_sc_start[c * DI * DSTATE + i] = s;
        s = g_sc_prod[c * DI * DSTATE + i] * s + g_sc_end[c * DI * DSTATE + i];
    }
}

__global__ void scan_pass2_kernel(const float* __restrict__ A_log)
{
    int gw   = threadIdx.x >> 5;
    int lane = threadIdx.x & 31;
    int n    = lane & 15;
    int ch   = (blockIdx.x * 4 + gw) * 2 + (lane >> 4);
    int c    = blockIdx.y;

    float Aval = -__expf(A_log[(size_t)ch * DSTATE + n]);
    float s = g_sc_start[(c * DI + ch) * DSTATE + n];
    int l0 = c * LCHUNK;
    for (int l = l0; l < l0 + LCHUNK; l++) {
        float dtv = g_dt [(size_t)l * DI + ch];
        float xcv = g_xc [(size_t)l * DI + ch];
        float Bv  = g_dbl[(size_t)l * DBL_W + DTRANK + n];
        float Cv  = g_dbl[(size_t)l * DBL_W + DTRANK + DSTATE + n];
        s = __expf(dtv * Aval) * s + dtv * Bv * xcv;
        float p = s * Cv;
        p += __shfl_xor_sync(0xffffffffu, p, 1);
        p += __shfl_xor_sync(0xffffffffu, p, 2);
        p += __shfl_xor_sync(0xffffffffu, p, 4);
        p += __shfl_xor_sync(0xffffffffu, p, 8);
        if (n == 0) g_y[(size_t)l * DI + ch] = p;
    }
}

// ---------------- y = (y + xc*D) * silu(z), fused [h|l] split --------------
__global__ void y_epi_split_kernel(const float* __restrict__ Dp)
{
    int idx = blockIdx.x * blockDim.x + threadIdx.x;
    int l = idx / DI;
    int d = idx - l * DI;
    float z  = g_xz[(size_t)l * 2 * DI + DI + d];
    float yv = g_y[idx] + g_xc[idx] * Dp[d];
    yv *= z / (1.f + __expf(-z));
    __nv_bfloat16 h = __float2bfloat16(yv);
    __nv_bfloat16 lo = __float2bfloat16(yv - __bfloat162float(h));
    __nv_bfloat16* row = g_y_s + (size_t)l * 2 * DI;
    row[d]      = h;
    row[DI + d] = lo;
}

// ---------------- split-K combines -----------------------------------------
__global__ void combine_h_kernel()
{
    int idx = blockIdx.x * blockDim.x + threadIdx.x;
    const int S = L_SEQ * DM;
    float a = g_part[idx]         + g_part[idx + S]     + g_part[idx + 2 * S];
    float b = g_part[idx + 3 * S] + g_part[idx + 4 * S] + g_part[idx + 5 * S];
    g_h[idx] += a + b;
}

__global__ void combine_dbl_kernel()
{
    int idx = blockIdx.x * blockDim.x + threadIdx.x;
    const int S = L_SEQ * DBL_W;
    float a = 0.f;
    #pragma unroll
    for (int z = 0; z < XPJ_SPLITK; z++) a += g_dblp[z * S + idx];
    g_dbl[idx] = a;
}

// ---------------- fp32 TN GEMM (dt_proj only) ------------------------------
#define GBM 128
#define GBN 64
#define GBK 16

template<int EPI>
__global__ __launch_bounds__(256)
void gemm_tn(const float* __restrict__ A, int lda,
             const float* __restrict__ B, int ldb,
             float* __restrict__ C, int ldc,
             int N, int K, const float* __restrict__ bias)
{
    __shared__ float As[GBK][GBM + 4];
    __shared__ float Bs[GBK][GBN + 4];

    const int bm  = blockIdx.y * GBM;
    const int bn  = blockIdx.x * GBN;
    const int tid = threadIdx.x;
    const int tx  = tid & 15;
    const int ty  = tid >> 4;
    const int a_row = tid >> 1;
    const int a_k   = (tid & 1) * 8;
    const int b_row = tid >> 2;
    const int b_k   = (tid & 3) * 4;

    float acc[8][4];
    #pragma unroll
    for (int i = 0; i < 8; i++)
        #pragma unroll
        for (int j = 0; j < 4; j++) acc[i][j] = 0.f;

    const float* Aptr = A + (size_t)(bm + a_row) * lda + a_k;
    const int gbn = bn + b_row;
    const float* Bptr = (gbn < N) ? (B + (size_t)gbn * ldb + b_k) : 0;

    for (int k0 = 0; k0 < K; k0 += GBK) {
        float4 av0 = *(const float4*)(Aptr + k0);
        float4 av1 = *(const float4*)(Aptr + k0 + 4);
        float4 bv  = Bptr ? *(const float4*)(Bptr + k0)
                          : make_float4(0.f, 0.f, 0.f, 0.f);

        As[a_k + 0][a_row] = av0.x; As[a_k + 1][a_row] = av0.y;
        As[a_k + 2][a_row] = av0.z; As[a_k + 3][a_row] = av0.w;
        As[a_k + 4][a_row] = av1.x; As[a_k + 5][a_row] = av1.y;
        As[a_k + 6][a_row] = av1.z; As[a_k + 7][a_row] = av1.w;
        Bs[b_k + 0][b_row] = bv.x;  Bs[b_k + 1][b_row] = bv.y;
        Bs[b_k + 2][b_row] = bv.z;  Bs[b_k + 3][b_row] = bv.w;
        __syncthreads();

        #pragma unroll
        for (int kk = 0; kk < GBK; kk++) {
            float ar[8], br[4];
            #pragma unroll
            for (int i = 0; i < 8; i++) ar[i] = As[kk][ty * 8 + i];
            #pragma unroll
            for (int j = 0; j < 4; j++) br[j] = Bs[kk][tx * 4 + j];
            #pragma unroll
            for (int i = 0; i < 8; i++)
                #pragma unroll
                for (int j = 0; j < 4; j++)
                    acc[i][j] = fmaf(ar[i], br[j], acc[i][j]);
        }
        __syncthreads();
    }

    #pragma unroll
    for (int i = 0; i < 8; i++) {
        int m = bm + ty * 8 + i;
        #pragma unroll
        for (int j = 0; j < 4; j++) {
            int n = bn + tx * 4 + j;
            if (n < N) {
                float v = acc[i][j];
                if (EPI == 1) {
                    v += bias[n];
                    v = fmaxf(v, 0.f) + log1pf(__expf(-fabsf(v)));
                }
                C[(size_t)m * ldc + n] = v;
            }
        }
    }
}

// ---------------- bf16 HMMA GEMM, templated N tile, 4-stage pair loop ------
#define TCM 128
#define TCK 32

__device__ __forceinline__ void cp_async16(uint32_t s, const void* g)
{
    asm volatile("cp.async.cg.shared.global [%0], [%1], 16;\n"
                 :: "r"(s), "l"(g));
}
__device__ __forceinline__ void cp_commit(){ asm volatile("cp.async.commit_group;\n" ::: "memory"); }
template<int N> __device__ __forceinline__ void cp_wait(){ asm volatile("cp.async.wait_group %0;\n" :: "n"(N) : "memory"); }

__device__ __forceinline__ void ldsm_x4(uint32_t* r, uint32_t addr)
{
    asm volatile("ldmatrix.sync.aligned.m8n8.x4.shared.b16 {%0,%1,%2,%3}, [%4];"
                 : "=r"(r[0]), "=r"(r[1]), "=r"(r[2]), "=r"(r[3]) : "r"(addr));
}
__device__ __forceinline__ void mma16816(float* c, const uint32_t* a, const uint32_t* b)
{
    asm volatile(
        "mma.sync.aligned.m16n8k16.row.col.f32.bf16.bf16.f32 "
        "{%0,%1,%2,%3}, {%4,%5,%6,%7}, {%8,%9}, {%0,%1,%2,%3};"
        : "+f"(c[0]), "+f"(c[1]), "+f"(c[2]), "+f"(c[3])
        : "r"(a[0]), "r"(a[1]), "r"(a[2]), "r"(a[3]), "r"(b[0]), "r"(b[1]));
}

__device__ __forceinline__ uint32_t swz(int row, int chunk){
    return (uint32_t)(row * 64 + ((chunk ^ ((row >> 1) & 3)) * 16));
}

template<int TN>
__global__ __launch_bounds__(TN == 64 ? 128 : 256, TN == 64 ? 4 : 2)
void mma_gemm(const __nv_bfloat16* __restrict__ A,
              const __nv_bfloat16* __restrict__ B,
              float* __restrict__ C, int ldc, int N, int Kreal,
              int cps, long long partStride)
{
    constexpr int NT   = (TN == 64) ? 128 : 256;
    constexpr int ASZ  = TCM * 64;
    constexpr int BSZ  = TN * 64;
    constexpr int STG  = ASZ + BSZ;
    constexpr int AI   = (TCM * 4) / NT;
    constexpr int BI   = (TN * 4) / NT;

    extern __shared__ __align__(16) char sm[];
    const uint32_t sbase = s2u(sm);
    const int tid  = threadIdx.x;
    const int wid  = tid >> 5, lane = tid & 31;
    const int wm   = wid & 1;
    const int wn   = wid >> 1;
    const int bm   = blockIdx.x * TCM;
    const int bn   = blockIdx.y * TN;
    const int KC   = Kreal / TCK;
    const int c0   = blockIdx.z * cps;
    const int c1   = c0 + cps;
    C += (long long)blockIdx.z * partStride;

    const int lda = 2 * Kreal;

    const __nv_bfloat16* Ag[AI]; uint32_t sa[AI];
    #pragma unroll
    for (int i = 0; i < AI; i++) {
        int v = tid + i * NT, r = v >> 2, k8 = v & 3;
        Ag[i] = A + (size_t)(bm + r) * lda + k8 * 8;
        sa[i] = sbase + swz(r, k8);
    }
    const __nv_bfloat16* Bg[BI]; uint32_t sb[BI];
    #pragma unroll
    for (int i = 0; i < BI; i++) {
        int v = tid + i * NT, r = v >> 2, k8 = v & 3;
        Bg[i] = B + (size_t)(bn + r) * lda + k8 * 8;
        sb[i] = sbase + ASZ + swz(r, k8);
    }

    float acc[4][4][4];
    #pragma unroll
    for (int i = 0; i < 4; i++)
        #pragma unroll
        for (int j = 0; j < 4; j++)
            #pragma unroll
            for (int t = 0; t < 4; t++) acc[i][j][t] = 0.f;

    const int a_row = wm * 64 + (lane & 15);
    const int a_k8s = lane >> 4;
    const int b_row = wn * 32 + (lane & 7) + ((lane >> 4) << 3);
    const int b_k8s = (lane >> 3) & 1;

    #define LOAD_STAGE(cc) do { \
        uint32_t so = (uint32_t)(((cc) - c0) & 3) * STG; \
        int ac = ((cc) < 2*KC ? (cc) : (cc) - 2*KC) * TCK; \
        int bc = ((cc) < KC   ? (cc) : (cc) - KC)   * TCK; \
        _Pragma("unroll") \
        for (int i = 0; i < AI; i++) cp_async16(sa[i] + so, Ag[i] + ac); \
        _Pragma("unroll") \
        for (int i = 0; i < BI; i++) cp_async16(sb[i] + so, Bg[i] + bc); \
        cp_commit(); \
    } while (0)

    #define MATH_STAGE(cc) do { \
        const uint32_t sA = sbase + (uint32_t)(((cc) - c0) & 3) * STG; \
        const uint32_t sB = sA + ASZ; \
        _Pragma("unroll") \
        for (int k16 = 0; k16 < 2; k16++) { \
            uint32_t afrag[4][4]; \
            _Pragma("unroll") \
            for (int mt = 0; mt < 4; mt++) { \
                int row = a_row + mt * 16; \
                ldsm_x4(afrag[mt], sA + swz(row, k16 * 2 + a_k8s)); \
            } \
            uint32_t bfrag[4][2]; \
            _Pragma("unroll") \
            for (int np = 0; np < 2; np++) { \
                int row = b_row + np * 16; \
                uint32_t t[4]; \
                ldsm_x4(t, sB + swz(row, k16 * 2 + b_k8s)); \
                bfrag[np * 2 + 0][0] = t[0]; bfrag[np * 2 + 0][1] = t[1]; \
                bfrag[np * 2 + 1][0] = t[2]; bfrag[np * 2 + 1][1] = t[3]; \
            } \
            _Pragma("unroll") \
            for (int mt = 0; mt < 4; mt++) \
                _Pragma("unroll") \
                for (int nt = 0; nt < 4; nt++) \
                    mma16816(acc[mt][nt], afrag[mt], bfrag[nt]); \
        } \
    } while (0)

    LOAD_STAGE(c0);
    if (c1 - c0 > 1) LOAD_STAGE(c0 + 1);

    for (int c = c0; c < c1; c += 2) {
        cp_wait<0>();
        __syncthreads();
        if (c + 2 < c1) { LOAD_STAGE(c + 2); LOAD_STAGE(c + 3); }
        MATH_STAGE(c);
        MATH_STAGE(c + 1);
    }
    #undef LOAD_STAGE
    #undef MATH_STAGE

    const int erow = lane >> 2;
    const int ecol = (lane & 3) * 2;
    #pragma unroll
    for (int mt = 0; mt < 4; mt++) {
        #pragma unroll
        for (int nt = 0; nt < 4; nt++) {
            int m0 = bm + wm * 64 + mt * 16 + erow;
            int n0 = bn + wn * 32 + nt * 8 + ecol;
            if (n0 < N) {
                float* p0 = C + (size_t)m0 * ldc + n0;
                float* p1 = p0 + 8 * ldc;
                *(float2*)p0 = make_float2(acc[mt][nt][0], acc[mt][nt][1]);
                *(float2*)p1 = make_float2(acc[mt][nt][2], acc[mt][nt][3]);
            }
        }
    }
}

#define SMEM64  (4 * (TCM*64 + 64*64))    // 49152
#define SMEM128 (4 * (TCM*64 + 128*64))   // 65536

// ---------------- orchestration --------------------------------------------
extern "C" void kernel_launch(void* const* d_in, const int* in_sizes, int n_in,
                              void* d_out, int out_size)
{
    const int*   ids        = (const int*)  d_in[0];
    const float* emb        = (const float*)d_in[1];
    const float* in_proj_w  = (const float*)d_in[2];
    const float* conv_w     = (const float*)d_in[3];
    const float* conv_b     = (const float*)d_in[4];
    const float* x_proj_w   = (const float*)d_in[5];
    const float* dt_proj_w  = (const float*)d_in[6];
    const float* dt_proj_b  = (const float*)d_in[7];
    const float* A_log      = (const float*)d_in[8];
    const float* D_param    = (const float*)d_in[9];
    const float* out_proj_w = (const float*)d_in[10];
    const float* norm_w     = (const float*)d_in[11];
    const float* norm_f_w   = (const float*)d_in[12];
    float* logits = (float*)d_out;

    // idempotent, called every time (no static guards per harness rules)
    cudaFuncSetAttribute(mma_gemm<64>,
                         cudaFuncAttributeMaxDynamicSharedMemorySize, SMEM64);
    cudaFuncSetAttribute(mma_gemm<128>,
                         cudaFuncAttributeMaxDynamicSharedMemorySize, SMEM128);

    float *h, *xz, *xc, *dbl, *dblp, *dt, *y, *part;
    cudaGetSymbolAddress((void**)&h,    g_h);
    cudaGetSymbolAddress((void**)&xz,   g_xz);
    cudaGetSymbolAddress((void**)&xc,   g_xc);
    cudaGetSymbolAddress((void**)&dbl,  g_dbl);
    cudaGetSymbolAddress((void**)&dblp, g_dblp);
    cudaGetSymbolAddress((void**)&dt,   g_dt);
    cudaGetSymbolAddress((void**)&y,    g_y);
    cudaGetSymbolAddress((void**)&part, g_part);

    __nv_bfloat16 *emb_s, *hn_s, *inw_s, *y_s, *outw_s, *xw_s;
    cudaGetSymbolAddress((void**)&emb_s,  g_emb_s);
    cudaGetSymbolAddress((void**)&hn_s,   g_hn_s);
    cudaGetSymbolAddress((void**)&inw_s,  g_inw_s);
    cudaGetSymbolAddress((void**)&y_s,    g_y_s);
    cudaGetSymbolAddress((void**)&outw_s, g_outw_s);
    cudaGetSymbolAddress((void**)&xw_s,   g_xw_s);

    embed_kernel<<<L_SEQ, DM / 4>>>(ids, emb);

    for (int i = 0; i < NLAYER; i++) {
        rmsnorm_split_kernel<<<L_SEQ, 256>>>(h, hn_s, norm_w + (size_t)i * DM);
        split2_kernel<<<(2 * DI * DM / 4) / 256, 256>>>(
            in_proj_w + (size_t)i * 2 * DI * DM, inw_s, 2 * DI, DM,
            (long long)2 * DI * DM / 4);

        // xz = hn @ in_proj_w^T   (1024 x 3072, K=768)
        {
            dim3 g1(L_SEQ / TCM, 2 * DI / 64, 1);
            mma_gemm<64><<<g1, 128, SMEM64>>>(hn_s, inw_s, xz, 2 * DI, 2 * DI, DM,
                                              3 * (DM / TCK), 0);
        }

        conv_silu_kernel<<<(L_SEQ * DI) / 256, 256>>>(
            conv_w + (size_t)i * DI * DCONV, conv_b + (size_t)i * DI);

        split2_kernel<<<(128 * DI / 4) / 256, 256>>>(
            x_proj_w + (size_t)i * DBL_W * DI, xw_s, DBL_W, DI,
            (long long)128 * DI / 4);

        // dbl = xc @ x_proj_w^T   (split-K=9, cps=16)
        {
            dim3 g2(L_SEQ / TCM, 2, XPJ_SPLITK);
            mma_gemm<64><<<g2, 128, SMEM64>>>(y_s, xw_s, dblp, DBL_W, DBL_W, DI,
                                              3 * (DI / TCK) / XPJ_SPLITK,
                                              (long long)L_SEQ * DBL_W);
        }
        combine_dbl_kernel<<<(L_SEQ * DBL_W) / 256, 256>>>();

        // dt = softplus(dbl[:, :48] @ dt_proj_w^T + b)
        {
            dim3 g3((DI + GBN - 1) / GBN, L_SEQ / GBM);
            gemm_tn<1><<<g3, 256>>>(dbl, DBL_W,
                                    dt_proj_w + (size_t)i * DI * DTRANK, DTRANK,
                                    dt, DI, DI, DTRANK,
                                    dt_proj_b + (size_t)i * DI);
        }

        // chunked selective scan
        {
            const float* Al = A_log + (size_t)i * DI * DSTATE;
            dim3 gs(DI / 8, NCHUNK);
            scan_pass1_kernel<<<gs, 128>>>(Al);
            scan_fix_kernel<<<(DI * DSTATE) / 256, 256>>>();
            scan_pass2_kernel<<<gs, 128>>>(Al);
        }

        y_epi_split_kernel<<<(L_SEQ * DI) / 256, 256>>>(D_param + (size_t)i * DI);

        split2_kernel<<<(DM * DI / 4) / 256, 256>>>(
            out_proj_w + (size_t)i * DM * DI, outw_s, DM, DI,
            (long long)DM * DI / 4);

        // part[z] = y @ out_proj_w^T, split-K=6 (cps=24)
        {
            dim3 g4(L_SEQ / TCM, DM / 64, 6);
            mma_gemm<64><<<g4, 128, SMEM64>>>(y_s, outw_s, part, DM, DM, DI,
                                              3 * (DI / TCK) / 6,
                                              (long long)L_SEQ * DM);
        }
        combine_h_kernel<<<(L_SEQ * DM) / 256, 256>>>();
    }

    rmsnorm_split_kernel<<<L_SEQ, 256>>>(h, hn_s, norm_f_w);
    {
        long long tot4 = (long long)VOCAB_PAD * DM / 4;
        split2_kernel<<<(unsigned)((tot4 + 255) / 256), 256>>>(emb, emb_s, VOCAB, DM, tot4);
    }

    // logits = hn @ emb^T   (1024 x 50280, K=768) — TN=128 tile
    {
        dim3 g5(L_SEQ / TCM, VOCAB_PAD / 128, 1);
        mma_gemm<128><<<g5, 256, SMEM128>>>(hn_s, emb_s, logits, VOCAB, VOCAB, DM,
                                            3 * (DM / TCK), 0);
    }
}